// round 1
// baseline (speedup 1.0000x reference)
#include <cuda_runtime.h>
#include <cuda_bf16.h>

// BatchHardTripletLoss: N=8192, D=128 fp32 embeddings, integer labels.
// loss = mean over valid anchors of relu(hardest_pos - hardest_neg + 0.3)
// Strategy: SGEMM-style fp32 Gram tiling with fused masked max/min reduction
// in squared-distance space (sqrt deferred to the per-row finalize).

#define MAXN 8192
#define DDIM 128
#define BM 32
#define BN 128
#define TM 4
#define TN 8
#define NTHREADS 128        // (BM/TM)*(BN/TN) = 8*16
#define SROW 132            // padded shared row stride in floats (33 float4s)

// Scratch (no device allocation allowed -> __device__ globals)
__device__ float g_sqn[MAXN];
__device__ float g_hp[MAXN];   // max over positives of (sqb - 2*dot), or -1e30
__device__ float g_hn[MAXN];   // min over negatives of (sqb - 2*dot), or +1e30
__device__ int   g_lab[MAXN];
__device__ int   g_is64;

// ---------------------------------------------------------------------------
// Detect whether the label buffer is int64 (little-endian: odd 32-bit words
// are all zero for labels in [0,1024)) or int32. Reads exactly n words, which
// is safe for both layouts.
__global__ void detect_kernel(const int* __restrict__ words, int n) {
    __shared__ int any_odd;
    if (threadIdx.x == 0) any_odd = 0;
    __syncthreads();
    int local = 0;
    for (int i = 1 + 2 * (int)threadIdx.x; i < n; i += 2 * blockDim.x)
        local |= words[i];
    if (local) atomicOr(&any_odd, 1);
    __syncthreads();
    if (threadIdx.x == 0) g_is64 = (any_odd == 0) ? 1 : 0;
}

__global__ void prep_labels(const int* __restrict__ words, int n) {
    int i = blockIdx.x * blockDim.x + threadIdx.x;
    if (i < n) {
        int stride64 = g_is64;
        g_lab[i] = words[stride64 ? (2 * i) : i];
    }
}

// ---------------------------------------------------------------------------
// Per-row squared norms: one warp per row, one float4 per lane (D=128).
__global__ void sqnorm_kernel(const float4* __restrict__ emb4, int n) {
    int row  = blockIdx.x * 8 + (threadIdx.x >> 5);
    int lane = threadIdx.x & 31;
    if (row < n) {
        float4 v = emb4[row * 32 + lane];
        float s = v.x * v.x + v.y * v.y + v.z * v.z + v.w * v.w;
        #pragma unroll
        for (int o = 16; o > 0; o >>= 1)
            s += __shfl_xor_sync(0xFFFFFFFFu, s, o);
        if (lane == 0) g_sqn[row] = s;
    }
}

// ---------------------------------------------------------------------------
// Main fused kernel: for a BM-row stripe, stream all BN-column tiles,
// compute dot products via shared-memory tiling, and fold masked
// max/min of (sqb - 2*dot) into per-thread running hardest values.
__global__ void __launch_bounds__(NTHREADS)
hard_kernel(const float* __restrict__ emb, int n) {
    extern __shared__ float smem[];
    float* sB   = smem;                       // BN x SROW  (col-major-in-k rows)
    float* sA   = smem + BN * SROW;           // BM x SROW
    float* sSqb = sA + BM * SROW;             // BN
    int*   sLb  = (int*)(sSqb + BN);          // BN

    const int tid = threadIdx.x;
    const int tx  = tid & 15;                 // 16 column groups
    const int ty  = tid >> 4;                 // 8 row groups
    const int rowBase = blockIdx.x * BM;

    const float4* emb4 = (const float4*)emb;
    float4* sA4 = (float4*)sA;
    float4* sB4 = (float4*)sB;

    // Load A stripe [BM x 128] into shared, natural [row][k] layout.
    #pragma unroll
    for (int i = 0; i < (BM * 32) / NTHREADS; i++) {
        int idx = tid + i * NTHREADS;
        int r = idx >> 5, kq = idx & 31;
        sA4[r * 33 + kq] = emb4[(rowBase + r) * 32 + kq];
    }

    int rl[TM];
    int ridx[TM];
    float hp[TM], hn[TM];
    #pragma unroll
    for (int i = 0; i < TM; i++) {
        ridx[i] = rowBase + ty * TM + i;
        rl[i]   = g_lab[ridx[i]];
        hp[i] = -1e30f;
        hn[i] =  1e30f;
    }

    for (int cb = 0; cb < n; cb += BN) {
        __syncthreads();   // previous tile's readers done before overwrite
        // Load B tile [BN x 128], natural [col][k] layout, coalesced float4.
        #pragma unroll
        for (int i = 0; i < (BN * 32) / NTHREADS; i++) {
            int idx = tid + i * NTHREADS;
            int c = idx >> 5, kq = idx & 31;
            sB4[c * 33 + kq] = emb4[(cb + c) * 32 + kq];
        }
        if (tid < BN) {
            sSqb[tid] = g_sqn[cb + tid];
            sLb[tid]  = g_lab[cb + tid];
        }
        __syncthreads();

        float acc[TM][TN];
        #pragma unroll
        for (int i = 0; i < TM; i++)
            #pragma unroll
            for (int j = 0; j < TN; j++)
                acc[i][j] = 0.0f;

        #pragma unroll 2
        for (int k4 = 0; k4 < 32; k4++) {
            float4 a[TM], b[TN];
            #pragma unroll
            for (int i = 0; i < TM; i++)
                a[i] = sA4[(ty * TM + i) * 33 + k4];
            #pragma unroll
            for (int j = 0; j < TN; j++)
                b[j] = sB4[(tx + 16 * j) * 33 + k4];
            #pragma unroll
            for (int i = 0; i < TM; i++)
                #pragma unroll
                for (int j = 0; j < TN; j++) {
                    acc[i][j] = fmaf(a[i].x, b[j].x, acc[i][j]);
                    acc[i][j] = fmaf(a[i].y, b[j].y, acc[i][j]);
                    acc[i][j] = fmaf(a[i].z, b[j].z, acc[i][j]);
                    acc[i][j] = fmaf(a[i].w, b[j].w, acc[i][j]);
                }
        }

        // Epilogue: masked fold into running hardest values (d^2 - sqa space).
        #pragma unroll
        for (int j = 0; j < TN; j++) {
            int cl = tx + 16 * j;
            int c  = cb + cl;
            float sqb = sSqb[cl];
            int   lb  = sLb[cl];
            #pragma unroll
            for (int i = 0; i < TM; i++) {
                float d2p = fmaf(-2.0f, acc[i][j], sqb);
                bool same = (lb == rl[i]);
                if (same) {
                    if (c != ridx[i]) hp[i] = fmaxf(hp[i], d2p);
                } else {
                    hn[i] = fminf(hn[i], d2p);
                }
            }
        }
    }

    // Reduce across the 16 tx lanes sharing each row (xor<16 stays in-half).
    #pragma unroll
    for (int o = 1; o < 16; o <<= 1) {
        #pragma unroll
        for (int i = 0; i < TM; i++) {
            hp[i] = fmaxf(hp[i], __shfl_xor_sync(0xFFFFFFFFu, hp[i], o));
            hn[i] = fminf(hn[i], __shfl_xor_sync(0xFFFFFFFFu, hn[i], o));
        }
    }
    if (tx == 0) {
        #pragma unroll
        for (int i = 0; i < TM; i++) {
            g_hp[ridx[i]] = hp[i];
            g_hn[ridx[i]] = hn[i];
        }
    }
}

// ---------------------------------------------------------------------------
// Finalize: per-row sqrt + relu + mean over valid rows.
__global__ void finalize_kernel(float* __restrict__ out, int n) {
    __shared__ float s_sum[32];
    __shared__ float s_cnt[32];
    float sum = 0.0f, cnt = 0.0f;
    for (int r = threadIdx.x; r < n; r += blockDim.x) {
        float hpv = g_hp[r];
        float hnv = g_hn[r];
        if (hpv > -1e29f && hnv < 1e29f) {
            float sq = g_sqn[r];
            float dp = sqrtf(fmaxf(sq + hpv, 0.0f));
            float dn = sqrtf(fmaxf(sq + hnv, 0.0f));
            sum += fmaxf(dp - dn + 0.3f, 0.0f);
            cnt += 1.0f;
        }
    }
    int lane = threadIdx.x & 31;
    int wid  = threadIdx.x >> 5;
    #pragma unroll
    for (int o = 16; o > 0; o >>= 1) {
        sum += __shfl_xor_sync(0xFFFFFFFFu, sum, o);
        cnt += __shfl_xor_sync(0xFFFFFFFFu, cnt, o);
    }
    if (lane == 0) { s_sum[wid] = sum; s_cnt[wid] = cnt; }
    __syncthreads();
    if (threadIdx.x < 32) {
        int nw = blockDim.x >> 5;
        sum = (threadIdx.x < nw) ? s_sum[threadIdx.x] : 0.0f;
        cnt = (threadIdx.x < nw) ? s_cnt[threadIdx.x] : 0.0f;
        #pragma unroll
        for (int o = 16; o > 0; o >>= 1) {
            sum += __shfl_xor_sync(0xFFFFFFFFu, sum, o);
            cnt += __shfl_xor_sync(0xFFFFFFFFu, cnt, o);
        }
        if (threadIdx.x == 0)
            out[0] = (cnt > 0.0f) ? (sum / cnt) : 0.0f;
    }
}

// ---------------------------------------------------------------------------
extern "C" void kernel_launch(void* const* d_in, const int* in_sizes, int n_in,
                              void* d_out, int out_size) {
    const float* emb  = (const float*)d_in[0];
    const int*   labw = (const int*)d_in[1];
    int n = in_sizes[0] / DDIM;   // 8192

    const int smem_bytes = (BN * SROW + BM * SROW + BN) * (int)sizeof(float)
                         + BN * (int)sizeof(int);
    cudaFuncSetAttribute(hard_kernel,
                         cudaFuncAttributeMaxDynamicSharedMemorySize,
                         smem_bytes);

    detect_kernel<<<1, 256>>>(labw, n);
    prep_labels<<<(n + 255) / 256, 256>>>(labw, n);
    sqnorm_kernel<<<(n + 7) / 8, 256>>>((const float4*)emb, n);
    hard_kernel<<<n / BM, NTHREADS, smem_bytes>>>(emb, n);
    finalize_kernel<<<1, 1024>>>((float*)d_out, n);
}

// round 5
// speedup vs baseline: 2.3620x; 2.3620x over previous
#include <cuda_runtime.h>
#include <cuda_fp16.h>
#include <cstdint>

// BatchHardTripletLoss via fp16 hi/lo-split HMMA (mma.sync m16n8k16) GEMM.
// dot = hi.hi + hi.lo + lo.hi (fp32 accum); fused masked max/min epilogue in
// (sqb - 2*dot) space; sqrt deferred to finalize.
// NOTE: harness ptxas targets plain sm_103 (no 'a') -> no tcgen05; mma.sync only.

#define NROWS  8192
#define DDIM   128
#define SPLITS 16
#define ROWBLKS (NROWS / 128)          // 64
#define TPC     (ROWBLKS / SPLITS)     // 4 column tiles per CTA
#define PSTRB   528                    // smem row stride bytes (264 halfs) - conflict-free for ldmatrix

// ---------------- device scratch ----------------
__device__ __align__(16) __half g_P[NROWS * 256];   // [row][0:128]=hi, [128:256]=lo
__device__ float2 g_meta[NROWS];                    // (sqnorm, label bits)
__device__ int    g_lab[NROWS];
__device__ int    g_is64;
__device__ float  g_hpp[SPLITS * NROWS];
__device__ float  g_hnn[SPLITS * NROWS];

// ---------------- asm helpers ----------------
__device__ __forceinline__ uint32_t smem_u32(const void* p) {
    uint32_t a;
    asm("{ .reg .u64 t; cvta.to.shared.u64 t, %1; cvt.u32.u64 %0, t; }" : "=r"(a) : "l"(p));
    return a;
}
#define CP_ASYNC16(dst, src) \
    asm volatile("cp.async.cg.shared.global [%0], [%1], 16;" :: "r"(dst), "l"(src))
#define CP_COMMIT() asm volatile("cp.async.commit_group;" ::: "memory")
#define CP_WAIT0()  asm volatile("cp.async.wait_group 0;" ::: "memory")

#define LDSM4(R0, R1, R2, R3, ADDR) \
    asm volatile("ldmatrix.sync.aligned.m8n8.x4.shared.b16 {%0,%1,%2,%3}, [%4];" \
        : "=r"(R0), "=r"(R1), "=r"(R2), "=r"(R3) : "r"(ADDR))

#define MMA16816(C, A0, A1, A2, A3, B0, B1) \
    asm volatile("mma.sync.aligned.m16n8k16.row.col.f32.f16.f16.f32 " \
        "{%0,%1,%2,%3}, {%4,%5,%6,%7}, {%8,%9}, {%0,%1,%2,%3};" \
        : "+f"((C)[0]), "+f"((C)[1]), "+f"((C)[2]), "+f"((C)[3]) \
        : "r"(A0), "r"(A1), "r"(A2), "r"(A3), "r"(B0), "r"(B1))

// ---------------- prep kernels ----------------
__global__ void detect_kernel(const int* __restrict__ words, int n) {
    __shared__ int any_odd;
    if (threadIdx.x == 0) any_odd = 0;
    __syncthreads();
    int local = 0;
    for (int i = 1 + 2 * (int)threadIdx.x; i < n; i += 2 * blockDim.x) local |= words[i];
    if (local) atomicOr(&any_odd, 1);
    __syncthreads();
    if (threadIdx.x == 0) g_is64 = (any_odd == 0) ? 1 : 0;
}
__global__ void prep_labels(const int* __restrict__ words, int n) {
    int i = blockIdx.x * blockDim.x + threadIdx.x;
    if (i < n) g_lab[i] = words[g_is64 ? (2 * i) : i];
}
__global__ void meta_kernel(const float4* __restrict__ emb4, int n) {
    int row = blockIdx.x * 8 + (threadIdx.x >> 5);
    int lane = threadIdx.x & 31;
    if (row < n) {
        float4 v = emb4[row * 32 + lane];
        float s = v.x * v.x + v.y * v.y + v.z * v.z + v.w * v.w;
        #pragma unroll
        for (int o = 16; o > 0; o >>= 1) s += __shfl_xor_sync(0xFFFFFFFFu, s, o);
        if (lane == 0) g_meta[row] = make_float2(s, __int_as_float(g_lab[row]));
    }
}
// Pack fp16 hi/lo: P[row][k] = hi, P[row][128+k] = lo. Plain row-major.
__global__ void pack_kernel(const float* __restrict__ emb) {
    int c = blockIdx.x * blockDim.x + threadIdx.x;   // NROWS*16 threads, 8 k each
    int row = c >> 4;
    int k8 = (c & 15) * 8;
    const float4* p = (const float4*)(emb + row * DDIM + k8);
    float4 v0 = p[0], v1 = p[1];
    float v[8] = {v0.x, v0.y, v0.z, v0.w, v1.x, v1.y, v1.z, v1.w};
    __half hi[8], lo[8];
    #pragma unroll
    for (int i = 0; i < 8; i++) {
        hi[i] = __float2half_rn(v[i]);
        lo[i] = __float2half_rn(v[i] - __half2float(hi[i]));
    }
    *(uint4*)(g_P + row * 256 + k8)       = *(const uint4*)hi;
    *(uint4*)(g_P + row * 256 + 128 + k8) = *(const uint4*)lo;
}

// ---------------- main HMMA kernel ----------------
// smem: A 128x528B = 67584 | B stage0 67584 | B stage1 67584 | meta 2x1024
#define OFF_A     0
#define OFF_B0    67584
#define OFF_B1    135168
#define OFF_MT0   202752
#define OFF_MT1   203776
#define SMEM_TOTAL 204800

__global__ void __launch_bounds__(256, 1) hmma_hard_kernel() {
    extern __shared__ char smem[];
    const uint32_t sb = smem_u32(smem);
    const int tid = threadIdx.x, wid = tid >> 5, lane = tid & 31;
    const int rowblk = blockIdx.x & (ROWBLKS - 1);
    const int split  = blockIdx.x >> 6;
    const int rowbase = rowblk * 128;
    const int colbase = split * (TPC * 128);

    // ---- prologue: load A (rows x [hi|lo]) once ----
    {
        #pragma unroll
        for (int i = 0; i < 16; i++) {
            int idx = tid + i * 256;
            int r = idx >> 5, c = idx & 31;
            CP_ASYNC16(sb + OFF_A + r * PSTRB + c * 16,
                       g_P + (size_t)(rowbase + r) * 256 + c * 8);
        }
        CP_COMMIT();
    }
    // ---- B tile 0 + meta 0 ----
    {
        #pragma unroll
        for (int i = 0; i < 16; i++) {
            int idx = tid + i * 256;
            int r = idx >> 5, c = idx & 31;
            CP_ASYNC16(sb + OFF_B0 + r * PSTRB + c * 16,
                       g_P + (size_t)(colbase + r) * 256 + c * 8);
        }
        if (tid < 64)
            CP_ASYNC16(sb + OFF_MT0 + tid * 16, (const char*)(g_meta + colbase) + tid * 16);
        CP_COMMIT();
    }

    const int rg0 = rowbase + 16 * wid + (lane >> 2);
    const int rg1 = rg0 + 8;
    const int rl0 = g_lab[rg0];
    const int rl1 = g_lab[rg1];
    float hp0 = -1e30f, hp1 = -1e30f, hn0 = 1e30f, hn1 = 1e30f;

    // lane-fixed ldmatrix address components
    const uint32_t aAddr = sb + OFF_A
        + (uint32_t)(16 * wid + 8 * ((lane >> 3) & 1) + (lane & 7)) * PSTRB
        + (uint32_t)(8 * (lane >> 4)) * 2;
    const uint32_t bRowOff =
        (uint32_t)(8 * (lane >> 4) + (lane & 7)) * PSTRB
        + (uint32_t)(8 * ((lane >> 3) & 1)) * 2;

    for (int t = 0; t < TPC; t++) {
        CP_WAIT0();            // tile t (and A) resident
        __syncthreads();       // all threads done with stage t^1 from iter t-1

        if (t + 1 < TPC) {     // prefetch B(t+1)+meta into the other stage
            const uint32_t dstB = sb + (((t + 1) & 1) ? OFF_B1 : OFF_B0);
            const int cb = colbase + (t + 1) * 128;
            #pragma unroll
            for (int i = 0; i < 16; i++) {
                int idx = tid + i * 256;
                int r = idx >> 5, c = idx & 31;
                CP_ASYNC16(dstB + r * PSTRB + c * 16,
                           g_P + (size_t)(cb + r) * 256 + c * 8);
            }
            if (tid < 64)
                CP_ASYNC16(sb + (((t + 1) & 1) ? OFF_MT1 : OFF_MT0) + tid * 16,
                           (const char*)(g_meta + cb) + tid * 16);
            CP_COMMIT();
        }

        const uint32_t bBase = sb + ((t & 1) ? OFF_B1 : OFF_B0) + bRowOff;

        float acc[16][4];
        #pragma unroll
        for (int f = 0; f < 16; f++)
            #pragma unroll
            for (int e = 0; e < 4; e++) acc[f][e] = 0.0f;

        // 3 sub-gemms: (hi,hi), (hi,lo), (lo,hi); K=128 each (8 k16-steps)
        #pragma unroll
        for (int g = 0; g < 3; g++) {
            const uint32_t aoff = (g == 2) ? 256u : 0u;   // bytes: 128 halfs
            const uint32_t boff = (g == 1) ? 256u : 0u;
            #pragma unroll
            for (int ks = 0; ks < 8; ks++) {
                uint32_t a0, a1, a2, a3;
                LDSM4(a0, a1, a2, a3, aAddr + aoff + (uint32_t)(32 * ks));
                #pragma unroll
                for (int nb = 0; nb < 8; nb++) {
                    uint32_t b0, b1, b2, b3;
                    LDSM4(b0, b1, b2, b3,
                          bBase + (uint32_t)(nb * 16 * PSTRB) + boff + (uint32_t)(32 * ks));
                    MMA16816(acc[2 * nb],     a0, a1, a2, a3, b0, b1);
                    MMA16816(acc[2 * nb + 1], a0, a1, a2, a3, b2, b3);
                }
            }
        }

        // fused epilogue: fold masked (sqb - 2*dot) into running hardest values
        {
            const float2* mp = (const float2*)(smem + ((t & 1) ? OFF_MT1 : OFF_MT0));
            const int cgb = colbase + t * 128;
            #pragma unroll
            for (int f = 0; f < 16; f++) {
                const int cl = 8 * f + 2 * (lane & 3);
                const float2 m0 = mp[cl];
                const float2 m1 = mp[cl + 1];
                const int c0 = cgb + cl, c1 = c0 + 1;
                const float d00 = fmaf(-2.0f, acc[f][0], m0.x);
                const float d01 = fmaf(-2.0f, acc[f][1], m1.x);
                const float d10 = fmaf(-2.0f, acc[f][2], m0.x);
                const float d11 = fmaf(-2.0f, acc[f][3], m1.x);
                const int l0 = __float_as_int(m0.y);
                const int l1 = __float_as_int(m1.y);
                if (l0 == rl0) { if (c0 != rg0) hp0 = fmaxf(hp0, d00); }
                else hn0 = fminf(hn0, d00);
                if (l1 == rl0) { if (c1 != rg0) hp0 = fmaxf(hp0, d01); }
                else hn0 = fminf(hn0, d01);
                if (l0 == rl1) { if (c0 != rg1) hp1 = fmaxf(hp1, d10); }
                else hn1 = fminf(hn1, d10);
                if (l1 == rl1) { if (c1 != rg1) hp1 = fmaxf(hp1, d11); }
                else hn1 = fminf(hn1, d11);
            }
        }
    }

    // reduce across the 4 lanes of each row quad
    #pragma unroll
    for (int o = 1; o < 4; o <<= 1) {
        hp0 = fmaxf(hp0, __shfl_xor_sync(0xFFFFFFFFu, hp0, o));
        hp1 = fmaxf(hp1, __shfl_xor_sync(0xFFFFFFFFu, hp1, o));
        hn0 = fminf(hn0, __shfl_xor_sync(0xFFFFFFFFu, hn0, o));
        hn1 = fminf(hn1, __shfl_xor_sync(0xFFFFFFFFu, hn1, o));
    }
    if ((lane & 3) == 0) {
        g_hpp[split * NROWS + rg0] = hp0;
        g_hpp[split * NROWS + rg1] = hp1;
        g_hnn[split * NROWS + rg0] = hn0;
        g_hnn[split * NROWS + rg1] = hn1;
    }
}

// ---------------- finalize ----------------
__global__ void finalize_kernel(float* __restrict__ out, int n) {
    __shared__ float s_sum[32], s_cnt[32];
    float sum = 0.0f, cnt = 0.0f;
    for (int r = threadIdx.x; r < n; r += blockDim.x) {
        float hp = -1e30f, hn = 1e30f;
        #pragma unroll
        for (int s = 0; s < SPLITS; s++) {
            hp = fmaxf(hp, g_hpp[s * NROWS + r]);
            hn = fminf(hn, g_hnn[s * NROWS + r]);
        }
        if (hp > -1e29f && hn < 1e29f) {
            float sqa = g_meta[r].x;
            float dp = sqrtf(fmaxf(sqa + hp, 0.0f));
            float dn = sqrtf(fmaxf(sqa + hn, 0.0f));
            sum += fmaxf(dp - dn + 0.3f, 0.0f);
            cnt += 1.0f;
        }
    }
    int lane = threadIdx.x & 31, wid = threadIdx.x >> 5;
    #pragma unroll
    for (int o = 16; o > 0; o >>= 1) {
        sum += __shfl_xor_sync(0xFFFFFFFFu, sum, o);
        cnt += __shfl_xor_sync(0xFFFFFFFFu, cnt, o);
    }
    if (lane == 0) { s_sum[wid] = sum; s_cnt[wid] = cnt; }
    __syncthreads();
    if (threadIdx.x < 32) {
        int nw = blockDim.x >> 5;
        sum = (threadIdx.x < nw) ? s_sum[threadIdx.x] : 0.0f;
        cnt = (threadIdx.x < nw) ? s_cnt[threadIdx.x] : 0.0f;
        #pragma unroll
        for (int o = 16; o > 0; o >>= 1) {
            sum += __shfl_xor_sync(0xFFFFFFFFu, sum, o);
            cnt += __shfl_xor_sync(0xFFFFFFFFu, cnt, o);
        }
        if (threadIdx.x == 0) out[0] = (cnt > 0.0f) ? (sum / cnt) : 0.0f;
    }
}

// ---------------- launch ----------------
extern "C" void kernel_launch(void* const* d_in, const int* in_sizes, int n_in,
                              void* d_out, int out_size) {
    const float* emb = (const float*)d_in[0];
    const int* labw = (const int*)d_in[1];
    int n = in_sizes[0] / DDIM;   // 8192

    cudaFuncSetAttribute(hmma_hard_kernel,
                         cudaFuncAttributeMaxDynamicSharedMemorySize, SMEM_TOTAL);

    detect_kernel<<<1, 256>>>(labw, n);
    prep_labels<<<(n + 255) / 256, 256>>>(labw, n);
    meta_kernel<<<(n + 7) / 8, 256>>>((const float4*)emb, n);
    pack_kernel<<<(n * 16) / 256, 256>>>(emb);
    hmma_hard_kernel<<<ROWBLKS * SPLITS, 256, SMEM_TOTAL>>>();
    finalize_kernel<<<1, 1024>>>((float*)d_out, n);
}

// round 9
// speedup vs baseline: 3.7314x; 1.5798x over previous
#include <cuda_runtime.h>
#include <cuda_fp16.h>
#include <cstdint>

// BatchHardTripletLoss via fp16 hi/lo-split HMMA with Gram-symmetry halving:
// only upper-triangle 128x128 tiles are computed; each tile is folded both
// row-wise (anchor=row) and column-wise (anchor=col). Hardest-pos/neg kept as
// monotone-uint-encoded floats in global arrays updated with atomicMax/Min.

#define NROWS  8192
#define DDIM   128
#define ROWBLKS 64
#define GRID_MAIN 544     // sum_{bi} ceil((64-bi)/4)
#define PSTRB   528       // smem row stride bytes (264 halfs)

// ---------------- device scratch ----------------
__device__ __align__(16) __half g_P[NROWS * 256];   // [row][0:128]=hi, [128:256]=lo
__device__ float2 g_meta[NROWS];                    // (sqnorm, label bits)
__device__ int    g_lab[NROWS];
__device__ int    g_is64;
__device__ unsigned g_apos[NROWS];                  // encoded hardest-pos (max)
__device__ unsigned g_aneg[NROWS];                  // encoded hardest-neg (min)

// ---------------- helpers ----------------
__device__ __forceinline__ uint32_t smem_u32(const void* p) {
    uint32_t a;
    asm("{ .reg .u64 t; cvta.to.shared.u64 t, %1; cvt.u32.u64 %0, t; }" : "=r"(a) : "l"(p));
    return a;
}
__device__ __forceinline__ unsigned enc(float x) {
    int i = __float_as_int(x);
    return (i < 0) ? (unsigned)(~i) : ((unsigned)i | 0x80000000u);
}
__device__ __forceinline__ float dec(unsigned u) {
    int i = (u & 0x80000000u) ? (int)(u ^ 0x80000000u) : ~(int)u;
    return __int_as_float(i);
}
#define CP_ASYNC16(dst, src) \
    asm volatile("cp.async.cg.shared.global [%0], [%1], 16;" :: "r"(dst), "l"(src))
#define CP_COMMIT() asm volatile("cp.async.commit_group;" ::: "memory")
#define CP_WAIT0()  asm volatile("cp.async.wait_group 0;" ::: "memory")
#define LDSM4(R0, R1, R2, R3, ADDR) \
    asm volatile("ldmatrix.sync.aligned.m8n8.x4.shared.b16 {%0,%1,%2,%3}, [%4];" \
        : "=r"(R0), "=r"(R1), "=r"(R2), "=r"(R3) : "r"(ADDR))
#define MMA16816(C, A0, A1, A2, A3, B0, B1) \
    asm volatile("mma.sync.aligned.m16n8k16.row.col.f32.f16.f16.f32 " \
        "{%0,%1,%2,%3}, {%4,%5,%6,%7}, {%8,%9}, {%0,%1,%2,%3};" \
        : "+f"((C)[0]), "+f"((C)[1]), "+f"((C)[2]), "+f"((C)[3]) \
        : "r"(A0), "r"(A1), "r"(A2), "r"(A3), "r"(B0), "r"(B1))

// ---------------- prep kernels ----------------
__global__ void detect_kernel(const int* __restrict__ words, int n) {
    __shared__ int any_odd;
    if (threadIdx.x == 0) any_odd = 0;
    __syncthreads();
    int local = 0;
    for (int i = 1 + 2 * (int)threadIdx.x; i < n; i += 2 * blockDim.x) local |= words[i];
    if (local) atomicOr(&any_odd, 1);
    __syncthreads();
    if (threadIdx.x == 0) g_is64 = (any_odd == 0) ? 1 : 0;
}
__global__ void prep_labels(const int* __restrict__ words, int n) {
    int i = blockIdx.x * blockDim.x + threadIdx.x;
    if (i < n) {
        g_lab[i] = words[g_is64 ? (2 * i) : i];
        g_apos[i] = enc(-1e30f);
        g_aneg[i] = enc(1e30f);
    }
}
__global__ void meta_kernel(const float4* __restrict__ emb4, int n) {
    int row = blockIdx.x * 8 + (threadIdx.x >> 5);
    int lane = threadIdx.x & 31;
    if (row < n) {
        float4 v = emb4[row * 32 + lane];
        float s = v.x * v.x + v.y * v.y + v.z * v.z + v.w * v.w;
        #pragma unroll
        for (int o = 16; o > 0; o >>= 1) s += __shfl_xor_sync(0xFFFFFFFFu, s, o);
        if (lane == 0) g_meta[row] = make_float2(s, __int_as_float(g_lab[row]));
    }
}
__global__ void pack_kernel(const float* __restrict__ emb) {
    int c = blockIdx.x * blockDim.x + threadIdx.x;
    int row = c >> 4;
    int k8 = (c & 15) * 8;
    const float4* p = (const float4*)(emb + row * DDIM + k8);
    float4 v0 = p[0], v1 = p[1];
    float v[8] = {v0.x, v0.y, v0.z, v0.w, v1.x, v1.y, v1.z, v1.w};
    __half hi[8], lo[8];
    #pragma unroll
    for (int i = 0; i < 8; i++) {
        hi[i] = __float2half_rn(v[i]);
        lo[i] = __float2half_rn(v[i] - __half2float(hi[i]));
    }
    *(uint4*)(g_P + row * 256 + k8)       = *(const uint4*)hi;
    *(uint4*)(g_P + row * 256 + 128 + k8) = *(const uint4*)lo;
}

// ---------------- main symmetric HMMA kernel ----------------
#define OFF_A     0
#define OFF_B0    67584
#define OFF_B1    135168
#define OFF_MT0   202752
#define OFF_MT1   203776
#define SMEM_TOTAL 204800

__global__ void __launch_bounds__(256, 1) hmma_sym_kernel() {
    extern __shared__ char smem[];
    const uint32_t sb = smem_u32(smem);
    const int tid = threadIdx.x, wid = tid >> 5, lane = tid & 31;

    // map blockIdx -> (bi, tile group g): row bi owns ceil((64-bi)/4) groups
    int id = blockIdx.x, bi = 0;
    for (; bi < ROWBLKS; bi++) {
        int cnt = (ROWBLKS - bi + 3) >> 2;
        if (id < cnt) break;
        id -= cnt;
    }
    const int bj0 = bi + 4 * id;
    const int nt = min(4, ROWBLKS - bj0);
    const int rowbase = bi * 128;

    // ---- prologue: A stripe (hi|lo) ----
    #pragma unroll
    for (int i = 0; i < 16; i++) {
        int idx = tid + i * 256;
        int r = idx >> 5, c = idx & 31;
        CP_ASYNC16(sb + OFF_A + r * PSTRB + c * 16,
                   g_P + (size_t)(rowbase + r) * 256 + c * 8);
    }
    CP_COMMIT();
    // ---- B tile 0 + meta 0 ----
    {
        const int cb = bj0 * 128;
        #pragma unroll
        for (int i = 0; i < 16; i++) {
            int idx = tid + i * 256;
            int r = idx >> 5, c = idx & 31;
            CP_ASYNC16(sb + OFF_B0 + r * PSTRB + c * 16,
                       g_P + (size_t)(cb + r) * 256 + c * 8);
        }
        if (tid < 64)
            CP_ASYNC16(sb + OFF_MT0 + tid * 16, (const char*)(g_meta + cb) + tid * 16);
        CP_COMMIT();
    }

    const int rg0 = rowbase + 16 * wid + (lane >> 2);
    const int rg1 = rg0 + 8;
    const float2 am0 = g_meta[rg0];
    const float2 am1 = g_meta[rg1];
    const int rl0 = __float_as_int(am0.y);
    const int rl1 = __float_as_int(am1.y);
    const float sqa0 = am0.x, sqa1 = am1.x;
    float hp0 = -1e30f, hp1 = -1e30f, hn0 = 1e30f, hn1 = 1e30f;

    const uint32_t aAddr = sb + OFF_A
        + (uint32_t)(16 * wid + 8 * ((lane >> 3) & 1) + (lane & 7)) * PSTRB
        + (uint32_t)(8 * (lane >> 4)) * 2;
    const uint32_t bRowOff =
        (uint32_t)(8 * (lane >> 4) + (lane & 7)) * PSTRB
        + (uint32_t)(8 * ((lane >> 3) & 1)) * 2;

    for (int t = 0; t < nt; t++) {
        CP_WAIT0();
        __syncthreads();

        if (t + 1 < nt) {
            const uint32_t dstB = sb + (((t + 1) & 1) ? OFF_B1 : OFF_B0);
            const int cb = (bj0 + t + 1) * 128;
            #pragma unroll
            for (int i = 0; i < 16; i++) {
                int idx = tid + i * 256;
                int r = idx >> 5, c = idx & 31;
                CP_ASYNC16(dstB + r * PSTRB + c * 16,
                           g_P + (size_t)(cb + r) * 256 + c * 8);
            }
            if (tid < 64)
                CP_ASYNC16(sb + (((t + 1) & 1) ? OFF_MT1 : OFF_MT0) + tid * 16,
                           (const char*)(g_meta + cb) + tid * 16);
            CP_COMMIT();
        }

        const uint32_t bBase = sb + ((t & 1) ? OFF_B1 : OFF_B0) + bRowOff;

        float acc[16][4];
        #pragma unroll
        for (int f = 0; f < 16; f++)
            #pragma unroll
            for (int e = 0; e < 4; e++) acc[f][e] = 0.0f;

        // fused hi/lo passes: 18 LDSM per 48 MMAs per k-step
        #pragma unroll
        for (int ks = 0; ks < 8; ks++) {
            uint32_t Ah[4], Al[4], Bh[8][4], Bl[8][4];
            LDSM4(Ah[0], Ah[1], Ah[2], Ah[3], aAddr + (uint32_t)(32 * ks));
            LDSM4(Al[0], Al[1], Al[2], Al[3], aAddr + 256u + (uint32_t)(32 * ks));
            #pragma unroll
            for (int nb = 0; nb < 8; nb++)
                LDSM4(Bh[nb][0], Bh[nb][1], Bh[nb][2], Bh[nb][3],
                      bBase + (uint32_t)(nb * 16 * PSTRB) + (uint32_t)(32 * ks));
            #pragma unroll
            for (int nb = 0; nb < 8; nb++)
                LDSM4(Bl[nb][0], Bl[nb][1], Bl[nb][2], Bl[nb][3],
                      bBase + (uint32_t)(nb * 16 * PSTRB) + 256u + (uint32_t)(32 * ks));
            #pragma unroll
            for (int nb = 0; nb < 8; nb++) {
                MMA16816(acc[2 * nb],     Ah[0], Ah[1], Ah[2], Ah[3], Bh[nb][0], Bh[nb][1]);
                MMA16816(acc[2 * nb + 1], Ah[0], Ah[1], Ah[2], Ah[3], Bh[nb][2], Bh[nb][3]);
            }
            #pragma unroll
            for (int nb = 0; nb < 8; nb++) {
                MMA16816(acc[2 * nb],     Al[0], Al[1], Al[2], Al[3], Bh[nb][0], Bh[nb][1]);
                MMA16816(acc[2 * nb + 1], Al[0], Al[1], Al[2], Al[3], Bh[nb][2], Bh[nb][3]);
            }
            #pragma unroll
            for (int nb = 0; nb < 8; nb++) {
                MMA16816(acc[2 * nb],     Ah[0], Ah[1], Ah[2], Ah[3], Bl[nb][0], Bl[nb][1]);
                MMA16816(acc[2 * nb + 1], Ah[0], Ah[1], Ah[2], Ah[3], Bl[nb][2], Bl[nb][3]);
            }
        }

        // ---- epilogue: row folds (registers) + column folds (shfl + atomics) ----
        {
            const float2* mp = (const float2*)(smem + ((t & 1) ? OFF_MT1 : OFF_MT0));
            const int cgb = (bj0 + t) * 128;
            #pragma unroll
            for (int f = 0; f < 16; f++) {
                const int cl = 8 * f + 2 * (lane & 3);
                const float2 m0 = mp[cl];
                const float2 m1 = mp[cl + 1];
                const int c0 = cgb + cl, c1 = c0 + 1;
                const int l0 = __float_as_int(m0.y);
                const int l1 = __float_as_int(m1.y);
                // row-anchor values: v = sqb - 2*dot
                const float v00 = fmaf(-2.0f, acc[f][0], m0.x);
                const float v01 = fmaf(-2.0f, acc[f][1], m1.x);
                const float v10 = fmaf(-2.0f, acc[f][2], m0.x);
                const float v11 = fmaf(-2.0f, acc[f][3], m1.x);
                // col-anchor values: w = sqa - 2*dot
                const float w00 = fmaf(-2.0f, acc[f][0], sqa0);
                const float w01 = fmaf(-2.0f, acc[f][1], sqa0);
                const float w10 = fmaf(-2.0f, acc[f][2], sqa1);
                const float w11 = fmaf(-2.0f, acc[f][3], sqa1);
                const bool s00 = (l0 == rl0), s01 = (l1 == rl0);
                const bool s10 = (l0 == rl1), s11 = (l1 == rl1);
                // row folds
                if (s00) { if (c0 != rg0) hp0 = fmaxf(hp0, v00); } else hn0 = fminf(hn0, v00);
                if (s01) { if (c1 != rg0) hp0 = fmaxf(hp0, v01); } else hn0 = fminf(hn0, v01);
                if (s10) { if (c0 != rg1) hp1 = fmaxf(hp1, v10); } else hn1 = fminf(hn1, v10);
                if (s11) { if (c1 != rg1) hp1 = fmaxf(hp1, v11); } else hn1 = fminf(hn1, v11);
                // col partials (this warp's 16 rows)
                float cp0 = fmaxf((s00 && c0 != rg0) ? w00 : -1e30f,
                                  (s10 && c0 != rg1) ? w10 : -1e30f);
                float cp1 = fmaxf((s01 && c1 != rg0) ? w01 : -1e30f,
                                  (s11 && c1 != rg1) ? w11 : -1e30f);
                float cn0 = fminf(s00 ? 1e30f : w00, s10 ? 1e30f : w10);
                float cn1 = fminf(s01 ? 1e30f : w01, s11 ? 1e30f : w11);
                #pragma unroll
                for (int o = 4; o < 32; o <<= 1) {
                    cp0 = fmaxf(cp0, __shfl_xor_sync(0xFFFFFFFFu, cp0, o));
                    cp1 = fmaxf(cp1, __shfl_xor_sync(0xFFFFFFFFu, cp1, o));
                    cn0 = fminf(cn0, __shfl_xor_sync(0xFFFFFFFFu, cn0, o));
                    cn1 = fminf(cn1, __shfl_xor_sync(0xFFFFFFFFu, cn1, o));
                }
                if (lane < 4) {
                    if (cp0 > -1e29f) atomicMax(&g_apos[c0], enc(cp0));
                    if (cp1 > -1e29f) atomicMax(&g_apos[c1], enc(cp1));
                    if (cn0 <  1e29f) atomicMin(&g_aneg[c0], enc(cn0));
                    if (cn1 <  1e29f) atomicMin(&g_aneg[c1], enc(cn1));
                }
            }
        }
    }

    // row folds -> global (reduce across the 4 lanes of each row quad first)
    #pragma unroll
    for (int o = 1; o < 4; o <<= 1) {
        hp0 = fmaxf(hp0, __shfl_xor_sync(0xFFFFFFFFu, hp0, o));
        hp1 = fmaxf(hp1, __shfl_xor_sync(0xFFFFFFFFu, hp1, o));
        hn0 = fminf(hn0, __shfl_xor_sync(0xFFFFFFFFu, hn0, o));
        hn1 = fminf(hn1, __shfl_xor_sync(0xFFFFFFFFu, hn1, o));
    }
    if ((lane & 3) == 0) {
        if (hp0 > -1e29f) atomicMax(&g_apos[rg0], enc(hp0));
        if (hp1 > -1e29f) atomicMax(&g_apos[rg1], enc(hp1));
        if (hn0 <  1e29f) atomicMin(&g_aneg[rg0], enc(hn0));
        if (hn1 <  1e29f) atomicMin(&g_aneg[rg1], enc(hn1));
    }
}

// ---------------- finalize ----------------
__global__ void finalize_kernel(float* __restrict__ out, int n) {
    __shared__ float s_sum[32], s_cnt[32];
    float sum = 0.0f, cnt = 0.0f;
    for (int r = threadIdx.x; r < n; r += blockDim.x) {
        float hp = dec(g_apos[r]);
        float hn = dec(g_aneg[r]);
        if (hp > -1e29f && hn < 1e29f) {
            float sqa = g_meta[r].x;
            float dp = sqrtf(fmaxf(sqa + hp, 0.0f));
            float dn = sqrtf(fmaxf(sqa + hn, 0.0f));
            sum += fmaxf(dp - dn + 0.3f, 0.0f);
            cnt += 1.0f;
        }
    }
    int lane = threadIdx.x & 31, wid = threadIdx.x >> 5;
    #pragma unroll
    for (int o = 16; o > 0; o >>= 1) {
        sum += __shfl_xor_sync(0xFFFFFFFFu, sum, o);
        cnt += __shfl_xor_sync(0xFFFFFFFFu, cnt, o);
    }
    if (lane == 0) { s_sum[wid] = sum; s_cnt[wid] = cnt; }
    __syncthreads();
    if (threadIdx.x < 32) {
        int nw = blockDim.x >> 5;
        sum = (threadIdx.x < nw) ? s_sum[threadIdx.x] : 0.0f;
        cnt = (threadIdx.x < nw) ? s_cnt[threadIdx.x] : 0.0f;
        #pragma unroll
        for (int o = 16; o > 0; o >>= 1) {
            sum += __shfl_xor_sync(0xFFFFFFFFu, sum, o);
            cnt += __shfl_xor_sync(0xFFFFFFFFu, cnt, o);
        }
        if (threadIdx.x == 0) out[0] = (cnt > 0.0f) ? (sum / cnt) : 0.0f;
    }
}

// ---------------- launch ----------------
extern "C" void kernel_launch(void* const* d_in, const int* in_sizes, int n_in,
                              void* d_out, int out_size) {
    const float* emb = (const float*)d_in[0];
    const int* labw = (const int*)d_in[1];
    int n = in_sizes[0] / DDIM;   // 8192

    cudaFuncSetAttribute(hmma_sym_kernel,
                         cudaFuncAttributeMaxDynamicSharedMemorySize, SMEM_TOTAL);

    detect_kernel<<<1, 256>>>(labw, n);
    prep_labels<<<(n + 255) / 256, 256>>>(labw, n);
    meta_kernel<<<(n + 7) / 8, 256>>>((const float4*)emb, n);
    pack_kernel<<<(n * 16) / 256, 256>>>(emb);
    hmma_sym_kernel<<<GRID_MAIN, 256, SMEM_TOTAL>>>();
    finalize_kernel<<<1, 1024>>>((float*)d_out, n);
}

// round 11
// speedup vs baseline: 4.5015x; 1.2064x over previous
#include <cuda_runtime.h>
#include <cuda_fp16.h>
#include <cstdint>

// BatchHardTripletLoss via fp16 hi/lo-split HMMA with Gram-symmetry halving.
// Upper-triangle 128x128 tiles only; each tile folded row-wise and column-wise.
// 512 threads/CTA (16 warps: 8 row-groups x 2 col-groups), smem-staged column
// reduction, global hardest-pos/neg as monotone-uint atomics.

#define NROWS  8192
#define DDIM   128
#define ROWBLKS 64
#define GRID_MAIN 544     // sum_{bi} ceil((64-bi)/4)
#define PSTRB   528       // smem row stride bytes (264 halfs)

// ---------------- device scratch ----------------
__device__ __align__(16) __half g_P[NROWS * 256];   // [row][0:128]=hi, [128:256]=lo
__device__ float2 g_meta[NROWS];                    // (sqnorm, label bits)
__device__ int    g_is64;
__device__ unsigned g_apos[NROWS];                  // encoded hardest-pos (max)
__device__ unsigned g_aneg[NROWS];                  // encoded hardest-neg (min)

// ---------------- helpers ----------------
__device__ __forceinline__ uint32_t smem_u32(const void* p) {
    uint32_t a;
    asm("{ .reg .u64 t; cvta.to.shared.u64 t, %1; cvt.u32.u64 %0, t; }" : "=r"(a) : "l"(p));
    return a;
}
__device__ __forceinline__ unsigned enc(float x) {
    int i = __float_as_int(x);
    return (i < 0) ? (unsigned)(~i) : ((unsigned)i | 0x80000000u);
}
__device__ __forceinline__ float dec(unsigned u) {
    int i = (u & 0x80000000u) ? (int)(u ^ 0x80000000u) : ~(int)u;
    return __int_as_float(i);
}
#define CP_ASYNC16(dst, src) \
    asm volatile("cp.async.cg.shared.global [%0], [%1], 16;" :: "r"(dst), "l"(src))
#define CP_COMMIT() asm volatile("cp.async.commit_group;" ::: "memory")
#define CP_WAIT0()  asm volatile("cp.async.wait_group 0;" ::: "memory")
#define LDSM4(R0, R1, R2, R3, ADDR) \
    asm volatile("ldmatrix.sync.aligned.m8n8.x4.shared.b16 {%0,%1,%2,%3}, [%4];" \
        : "=r"(R0), "=r"(R1), "=r"(R2), "=r"(R3) : "r"(ADDR))
#define MMA16816(C, A0, A1, A2, A3, B0, B1) \
    asm volatile("mma.sync.aligned.m16n8k16.row.col.f32.f16.f16.f32 " \
        "{%0,%1,%2,%3}, {%4,%5,%6,%7}, {%8,%9}, {%0,%1,%2,%3};" \
        : "+f"((C)[0]), "+f"((C)[1]), "+f"((C)[2]), "+f"((C)[3]) \
        : "r"(A0), "r"(A1), "r"(A2), "r"(A3), "r"(B0), "r"(B1))

// ---------------- prep kernels (fused to 3 launches before main) ----------------
__global__ void detect_kernel(const int* __restrict__ words, int n) {
    __shared__ int any_odd;
    if (threadIdx.x == 0) any_odd = 0;
    __syncthreads();
    int local = 0;
    for (int i = 1 + 2 * (int)threadIdx.x; i < n; i += 2 * blockDim.x) local |= words[i];
    if (local) atomicOr(&any_odd, 1);
    __syncthreads();
    if (threadIdx.x == 0) g_is64 = (any_odd == 0) ? 1 : 0;
}
// fused: labels + sqnorm meta + init of atomic arrays; one warp per row
__global__ void prep_meta_kernel(const int* __restrict__ words,
                                 const float4* __restrict__ emb4, int n) {
    int row  = blockIdx.x * 8 + (threadIdx.x >> 5);
    int lane = threadIdx.x & 31;
    if (row < n) {
        float4 v = emb4[row * 32 + lane];
        float s = v.x * v.x + v.y * v.y + v.z * v.z + v.w * v.w;
        #pragma unroll
        for (int o = 16; o > 0; o >>= 1) s += __shfl_xor_sync(0xFFFFFFFFu, s, o);
        if (lane == 0) {
            int lab = words[g_is64 ? (2 * row) : row];
            g_meta[row] = make_float2(s, __int_as_float(lab));
            g_apos[row] = enc(-1e30f);
            g_aneg[row] = enc(1e30f);
        }
    }
}
__global__ void pack_kernel(const float* __restrict__ emb) {
    int c = blockIdx.x * blockDim.x + threadIdx.x;
    int row = c >> 4;
    int k8 = (c & 15) * 8;
    const float4* p = (const float4*)(emb + row * DDIM + k8);
    float4 v0 = p[0], v1 = p[1];
    float v[8] = {v0.x, v0.y, v0.z, v0.w, v1.x, v1.y, v1.z, v1.w};
    __half hi[8], lo[8];
    #pragma unroll
    for (int i = 0; i < 8; i++) {
        hi[i] = __float2half_rn(v[i]);
        lo[i] = __float2half_rn(v[i] - __half2float(hi[i]));
    }
    *(uint4*)(g_P + row * 256 + k8)       = *(const uint4*)hi;
    *(uint4*)(g_P + row * 256 + 128 + k8) = *(const uint4*)lo;
}

// ---------------- main symmetric HMMA kernel ----------------
#define OFF_A     0
#define OFF_B0    67584
#define OFF_B1    135168
#define OFF_MT0   202752
#define OFF_MT1   203776
#define OFF_CBP   204800    // colbuf pos: 8 x 128 floats
#define OFF_CBN   208896    // colbuf neg: 8 x 128 floats
#define SMEM_TOTAL 212992

__global__ void __launch_bounds__(512, 1) hmma_sym_kernel() {
    extern __shared__ char smem[];
    const uint32_t sb = smem_u32(smem);
    const int tid = threadIdx.x, wid = tid >> 5, lane = tid & 31;
    const int wy = wid >> 1, wx = wid & 1;   // 8 row-groups x 2 col-groups

    // map blockIdx -> (bi, group of 4 column tiles)
    int id = blockIdx.x, bi = 0;
    for (; bi < ROWBLKS; bi++) {
        int cnt = (ROWBLKS - bi + 3) >> 2;
        if (id < cnt) break;
        id -= cnt;
    }
    const int bj0 = bi + 4 * id;
    const int nt = min(4, ROWBLKS - bj0);
    const int rowbase = bi * 128;

    // ---- prologue: A stripe (hi|lo), B tile 0, meta 0 ----
    #pragma unroll
    for (int i = 0; i < 8; i++) {
        int idx = tid + i * 512;
        int r = idx >> 5, c = idx & 31;
        CP_ASYNC16(sb + OFF_A + r * PSTRB + c * 16,
                   g_P + (size_t)(rowbase + r) * 256 + c * 8);
    }
    CP_COMMIT();
    {
        const int cb = bj0 * 128;
        #pragma unroll
        for (int i = 0; i < 8; i++) {
            int idx = tid + i * 512;
            int r = idx >> 5, c = idx & 31;
            CP_ASYNC16(sb + OFF_B0 + r * PSTRB + c * 16,
                       g_P + (size_t)(cb + r) * 256 + c * 8);
        }
        if (tid < 64)
            CP_ASYNC16(sb + OFF_MT0 + tid * 16, (const char*)(g_meta + cb) + tid * 16);
        CP_COMMIT();
    }

    const int rg0 = rowbase + 16 * wy + (lane >> 2);
    const int rg1 = rg0 + 8;
    const float2 am0 = g_meta[rg0];
    const float2 am1 = g_meta[rg1];
    const int rl0 = __float_as_int(am0.y);
    const int rl1 = __float_as_int(am1.y);
    const float sqa0 = am0.x, sqa1 = am1.x;
    float hp0 = -1e30f, hp1 = -1e30f, hn0 = 1e30f, hn1 = 1e30f;

    const uint32_t aAddr = sb + OFF_A
        + (uint32_t)(16 * wy + 8 * ((lane >> 3) & 1) + (lane & 7)) * PSTRB
        + (uint32_t)(8 * (lane >> 4)) * 2;
    const uint32_t bColOff = (uint32_t)(64 * wx) * PSTRB
        + (uint32_t)(8 * (lane >> 4) + (lane & 7)) * PSTRB
        + (uint32_t)(8 * ((lane >> 3) & 1)) * 2;

    float* sCBP = (float*)(smem + OFF_CBP);
    float* sCBN = (float*)(smem + OFF_CBN);

    for (int t = 0; t < nt; t++) {
        CP_WAIT0();
        __syncthreads();     // loads visible; colbuf from t-1 fully consumed

        if (t + 1 < nt) {    // prefetch next B + meta
            const uint32_t dstB = sb + (((t + 1) & 1) ? OFF_B1 : OFF_B0);
            const int cb = (bj0 + t + 1) * 128;
            #pragma unroll
            for (int i = 0; i < 8; i++) {
                int idx = tid + i * 512;
                int r = idx >> 5, c = idx & 31;
                CP_ASYNC16(dstB + r * PSTRB + c * 16,
                           g_P + (size_t)(cb + r) * 256 + c * 8);
            }
            if (tid < 64)
                CP_ASYNC16(sb + (((t + 1) & 1) ? OFF_MT1 : OFF_MT0) + tid * 16,
                           (const char*)(g_meta + cb) + tid * 16);
            CP_COMMIT();
        }

        const uint32_t bBase = sb + ((t & 1) ? OFF_B1 : OFF_B0) + bColOff;

        float acc[8][4];
        #pragma unroll
        for (int f = 0; f < 8; f++)
            #pragma unroll
            for (int e = 0; e < 4; e++) acc[f][e] = 0.0f;

        #pragma unroll
        for (int ks = 0; ks < 8; ks++) {
            uint32_t Ah[4], Al[4], Bf[4][4];
            LDSM4(Ah[0], Ah[1], Ah[2], Ah[3], aAddr + (uint32_t)(32 * ks));
            LDSM4(Al[0], Al[1], Al[2], Al[3], aAddr + 256u + (uint32_t)(32 * ks));
            #pragma unroll
            for (int nb = 0; nb < 4; nb++)
                LDSM4(Bf[nb][0], Bf[nb][1], Bf[nb][2], Bf[nb][3],
                      bBase + (uint32_t)(nb * 16 * PSTRB) + (uint32_t)(32 * ks));
            #pragma unroll
            for (int nb = 0; nb < 4; nb++) {
                MMA16816(acc[2 * nb],     Ah[0], Ah[1], Ah[2], Ah[3], Bf[nb][0], Bf[nb][1]);
                MMA16816(acc[2 * nb + 1], Ah[0], Ah[1], Ah[2], Ah[3], Bf[nb][2], Bf[nb][3]);
            }
            #pragma unroll
            for (int nb = 0; nb < 4; nb++) {
                MMA16816(acc[2 * nb],     Al[0], Al[1], Al[2], Al[3], Bf[nb][0], Bf[nb][1]);
                MMA16816(acc[2 * nb + 1], Al[0], Al[1], Al[2], Al[3], Bf[nb][2], Bf[nb][3]);
            }
            // reload same registers with lo-B fragments (short lifetime)
            #pragma unroll
            for (int nb = 0; nb < 4; nb++)
                LDSM4(Bf[nb][0], Bf[nb][1], Bf[nb][2], Bf[nb][3],
                      bBase + (uint32_t)(nb * 16 * PSTRB) + 256u + (uint32_t)(32 * ks));
            #pragma unroll
            for (int nb = 0; nb < 4; nb++) {
                MMA16816(acc[2 * nb],     Ah[0], Ah[1], Ah[2], Ah[3], Bf[nb][0], Bf[nb][1]);
                MMA16816(acc[2 * nb + 1], Ah[0], Ah[1], Ah[2], Ah[3], Bf[nb][2], Bf[nb][3]);
            }
        }

        // ---- epilogue: row folds in regs; column partials -> smem colbuf ----
        {
            const float2* mp = (const float2*)(smem + ((t & 1) ? OFF_MT1 : OFF_MT0));
            const int cgb = (bj0 + t) * 128;
            #pragma unroll
            for (int f = 0; f < 8; f++) {
                const int cl = 64 * wx + 8 * f + 2 * (lane & 3);
                const float2 m0 = mp[cl];
                const float2 m1 = mp[cl + 1];
                const int c0 = cgb + cl, c1 = c0 + 1;
                const int l0 = __float_as_int(m0.y);
                const int l1 = __float_as_int(m1.y);
                const float v00 = fmaf(-2.0f, acc[f][0], m0.x);
                const float v01 = fmaf(-2.0f, acc[f][1], m1.x);
                const float v10 = fmaf(-2.0f, acc[f][2], m0.x);
                const float v11 = fmaf(-2.0f, acc[f][3], m1.x);
                const float w00 = fmaf(-2.0f, acc[f][0], sqa0);
                const float w01 = fmaf(-2.0f, acc[f][1], sqa0);
                const float w10 = fmaf(-2.0f, acc[f][2], sqa1);
                const float w11 = fmaf(-2.0f, acc[f][3], sqa1);
                const bool s00 = (l0 == rl0), s01 = (l1 == rl0);
                const bool s10 = (l0 == rl1), s11 = (l1 == rl1);
                if (s00) { if (c0 != rg0) hp0 = fmaxf(hp0, v00); } else hn0 = fminf(hn0, v00);
                if (s01) { if (c1 != rg0) hp0 = fmaxf(hp0, v01); } else hn0 = fminf(hn0, v01);
                if (s10) { if (c0 != rg1) hp1 = fmaxf(hp1, v10); } else hn1 = fminf(hn1, v10);
                if (s11) { if (c1 != rg1) hp1 = fmaxf(hp1, v11); } else hn1 = fminf(hn1, v11);
                float cp0 = fmaxf((s00 && c0 != rg0) ? w00 : -1e30f,
                                  (s10 && c0 != rg1) ? w10 : -1e30f);
                float cp1 = fmaxf((s01 && c1 != rg0) ? w01 : -1e30f,
                                  (s11 && c1 != rg1) ? w11 : -1e30f);
                float cn0 = fminf(s00 ? 1e30f : w00, s10 ? 1e30f : w10);
                float cn1 = fminf(s01 ? 1e30f : w01, s11 ? 1e30f : w11);
                #pragma unroll
                for (int o = 4; o < 32; o <<= 1) {
                    cp0 = fmaxf(cp0, __shfl_xor_sync(0xFFFFFFFFu, cp0, o));
                    cp1 = fmaxf(cp1, __shfl_xor_sync(0xFFFFFFFFu, cp1, o));
                    cn0 = fminf(cn0, __shfl_xor_sync(0xFFFFFFFFu, cn0, o));
                    cn1 = fminf(cn1, __shfl_xor_sync(0xFFFFFFFFu, cn1, o));
                }
                if (lane < 4) {            // disjoint addresses: plain stores
                    sCBP[wy * 128 + cl]     = cp0;
                    sCBP[wy * 128 + cl + 1] = cp1;
                    sCBN[wy * 128 + cl]     = cn0;
                    sCBN[wy * 128 + cl + 1] = cn1;
                }
            }
        }
        __syncthreads();
        if (tid < 128) {     // fold 8 row-groups, one global RED pair per column
            const int c = (bj0 + t) * 128 + tid;
            float p = sCBP[tid], q = sCBN[tid];
            #pragma unroll
            for (int w = 1; w < 8; w++) {
                p = fmaxf(p, sCBP[w * 128 + tid]);
                q = fminf(q, sCBN[w * 128 + tid]);
            }
            if (p > -1e29f) atomicMax(&g_apos[c], enc(p));
            if (q <  1e29f) atomicMin(&g_aneg[c], enc(q));
        }
    }

    // row folds -> global (fold the 4 lanes of each row quad first)
    #pragma unroll
    for (int o = 1; o < 4; o <<= 1) {
        hp0 = fmaxf(hp0, __shfl_xor_sync(0xFFFFFFFFu, hp0, o));
        hp1 = fmaxf(hp1, __shfl_xor_sync(0xFFFFFFFFu, hp1, o));
        hn0 = fminf(hn0, __shfl_xor_sync(0xFFFFFFFFu, hn0, o));
        hn1 = fminf(hn1, __shfl_xor_sync(0xFFFFFFFFu, hn1, o));
    }
    if ((lane & 3) == 0) {
        if (hp0 > -1e29f) atomicMax(&g_apos[rg0], enc(hp0));
        if (hp1 > -1e29f) atomicMax(&g_apos[rg1], enc(hp1));
        if (hn0 <  1e29f) atomicMin(&g_aneg[rg0], enc(hn0));
        if (hn1 <  1e29f) atomicMin(&g_aneg[rg1], enc(hn1));
    }
}

// ---------------- finalize ----------------
__global__ void finalize_kernel(float* __restrict__ out, int n) {
    __shared__ float s_sum[32], s_cnt[32];
    float sum = 0.0f, cnt = 0.0f;
    for (int r = threadIdx.x; r < n; r += blockDim.x) {
        float hp = dec(g_apos[r]);
        float hn = dec(g_aneg[r]);
        if (hp > -1e29f && hn < 1e29f) {
            float sqa = g_meta[r].x;
            float dp = sqrtf(fmaxf(sqa + hp, 0.0f));
            float dn = sqrtf(fmaxf(sqa + hn, 0.0f));
            sum += fmaxf(dp - dn + 0.3f, 0.0f);
            cnt += 1.0f;
        }
    }
    int lane = threadIdx.x & 31, wid = threadIdx.x >> 5;
    #pragma unroll
    for (int o = 16; o > 0; o >>= 1) {
        sum += __shfl_xor_sync(0xFFFFFFFFu, sum, o);
        cnt += __shfl_xor_sync(0xFFFFFFFFu, cnt, o);
    }
    if (lane == 0) { s_sum[wid] = sum; s_cnt[wid] = cnt; }
    __syncthreads();
    if (threadIdx.x < 32) {
        int nw = blockDim.x >> 5;
        sum = (threadIdx.x < nw) ? s_sum[threadIdx.x] : 0.0f;
        cnt = (threadIdx.x < nw) ? s_cnt[threadIdx.x] : 0.0f;
        #pragma unroll
        for (int o = 16; o > 0; o >>= 1) {
            sum += __shfl_xor_sync(0xFFFFFFFFu, sum, o);
            cnt += __shfl_xor_sync(0xFFFFFFFFu, cnt, o);
        }
        if (threadIdx.x == 0) out[0] = (cnt > 0.0f) ? (sum / cnt) : 0.0f;
    }
}

// ---------------- launch (5 kernels: main is launch index 3) ----------------
extern "C" void kernel_launch(void* const* d_in, const int* in_sizes, int n_in,
                              void* d_out, int out_size) {
    const float* emb = (const float*)d_in[0];
    const int* labw = (const int*)d_in[1];
    int n = in_sizes[0] / DDIM;   // 8192

    cudaFuncSetAttribute(hmma_sym_kernel,
                         cudaFuncAttributeMaxDynamicSharedMemorySize, SMEM_TOTAL);

    detect_kernel<<<1, 256>>>(labw, n);
    prep_meta_kernel<<<(n + 7) / 8, 256>>>(labw, (const float4*)emb, n);
    pack_kernel<<<(n * 16) / 256, 256>>>(emb);
    hmma_sym_kernel<<<GRID_MAIN, 512, SMEM_TOTAL>>>();
    finalize_kernel<<<1, 1024>>>((float*)d_out, n);
}

// round 13
// speedup vs baseline: 4.6786x; 1.0393x over previous
#include <cuda_runtime.h>
#include <cuda_fp16.h>
#include <cstdint>

// BatchHardTripletLoss via fp16 hi/lo-split HMMA with Gram-symmetry halving.
// Upper-triangle 128x128 tiles; folded row-wise and column-wise.
// 256 threads/CTA, 8 warps as 4 row-groups x 2 col-groups, warp tile 32x64
// (12 LDSM.x4 per 48 MMAs per k-step -> smem pipe balanced with tensor pipe).

#define NROWS  8192
#define DDIM   128
#define ROWBLKS 64
#define GRID_MAIN 544     // sum_{bi} ceil((64-bi)/4)
#define PSTRB   528       // smem row stride bytes (264 halfs)

// ---------------- device scratch ----------------
__device__ __align__(16) __half g_P[NROWS * 256];   // [row][0:128]=hi, [128:256]=lo
__device__ float2 g_meta[NROWS];                    // (sqnorm, label bits)
__device__ int    g_is64;
__device__ unsigned g_apos[NROWS];                  // encoded hardest-pos (max)
__device__ unsigned g_aneg[NROWS];                  // encoded hardest-neg (min)

// ---------------- helpers ----------------
__device__ __forceinline__ uint32_t smem_u32(const void* p) {
    uint32_t a;
    asm("{ .reg .u64 t; cvta.to.shared.u64 t, %1; cvt.u32.u64 %0, t; }" : "=r"(a) : "l"(p));
    return a;
}
__device__ __forceinline__ unsigned enc(float x) {
    int i = __float_as_int(x);
    return (i < 0) ? (unsigned)(~i) : ((unsigned)i | 0x80000000u);
}
__device__ __forceinline__ float dec(unsigned u) {
    int i = (u & 0x80000000u) ? (int)(u ^ 0x80000000u) : ~(int)u;
    return __int_as_float(i);
}
#define CP_ASYNC16(dst, src) \
    asm volatile("cp.async.cg.shared.global [%0], [%1], 16;" :: "r"(dst), "l"(src))
#define CP_COMMIT() asm volatile("cp.async.commit_group;" ::: "memory")
#define CP_WAIT0()  asm volatile("cp.async.wait_group 0;" ::: "memory")
#define LDSM4(R0, R1, R2, R3, ADDR) \
    asm volatile("ldmatrix.sync.aligned.m8n8.x4.shared.b16 {%0,%1,%2,%3}, [%4];" \
        : "=r"(R0), "=r"(R1), "=r"(R2), "=r"(R3) : "r"(ADDR))
#define MMA16816(C, A0, A1, A2, A3, B0, B1) \
    asm volatile("mma.sync.aligned.m16n8k16.row.col.f32.f16.f16.f32 " \
        "{%0,%1,%2,%3}, {%4,%5,%6,%7}, {%8,%9}, {%0,%1,%2,%3};" \
        : "+f"((C)[0]), "+f"((C)[1]), "+f"((C)[2]), "+f"((C)[3]) \
        : "r"(A0), "r"(A1), "r"(A2), "r"(A3), "r"(B0), "r"(B1))

// ---------------- prep kernels ----------------
__global__ void detect_kernel(const int* __restrict__ words, int n) {
    __shared__ int any_odd;
    if (threadIdx.x == 0) any_odd = 0;
    __syncthreads();
    int local = 0;
    for (int i = 1 + 2 * (int)threadIdx.x; i < n; i += 2 * blockDim.x) local |= words[i];
    if (local) atomicOr(&any_odd, 1);
    __syncthreads();
    if (threadIdx.x == 0) g_is64 = (any_odd == 0) ? 1 : 0;
}
__global__ void prep_meta_kernel(const int* __restrict__ words,
                                 const float4* __restrict__ emb4, int n) {
    int row  = blockIdx.x * 8 + (threadIdx.x >> 5);
    int lane = threadIdx.x & 31;
    if (row < n) {
        float4 v = emb4[row * 32 + lane];
        float s = v.x * v.x + v.y * v.y + v.z * v.z + v.w * v.w;
        #pragma unroll
        for (int o = 16; o > 0; o >>= 1) s += __shfl_xor_sync(0xFFFFFFFFu, s, o);
        if (lane == 0) {
            int lab = words[g_is64 ? (2 * row) : row];
            g_meta[row] = make_float2(s, __int_as_float(lab));
            g_apos[row] = enc(-1e30f);
            g_aneg[row] = enc(1e30f);
        }
    }
}
__global__ void pack_kernel(const float* __restrict__ emb) {
    int c = blockIdx.x * blockDim.x + threadIdx.x;
    int row = c >> 4;
    int k8 = (c & 15) * 8;
    const float4* p = (const float4*)(emb + row * DDIM + k8);
    float4 v0 = p[0], v1 = p[1];
    float v[8] = {v0.x, v0.y, v0.z, v0.w, v1.x, v1.y, v1.z, v1.w};
    __half hi[8], lo[8];
    #pragma unroll
    for (int i = 0; i < 8; i++) {
        hi[i] = __float2half_rn(v[i]);
        lo[i] = __float2half_rn(v[i] - __half2float(hi[i]));
    }
    *(uint4*)(g_P + row * 256 + k8)       = *(const uint4*)hi;
    *(uint4*)(g_P + row * 256 + 128 + k8) = *(const uint4*)lo;
}

// ---------------- main symmetric HMMA kernel ----------------
#define OFF_A     0
#define OFF_B0    67584
#define OFF_B1    135168
#define OFF_MT0   202752
#define OFF_MT1   203776
#define OFF_CBP   204800    // colbuf pos: 4 x 128 floats
#define OFF_CBN   206848    // colbuf neg: 4 x 128 floats
#define SMEM_TOTAL 208896

__global__ void __launch_bounds__(256, 1) hmma_sym_kernel() {
    extern __shared__ char smem[];
    const uint32_t sb = smem_u32(smem);
    const int tid = threadIdx.x, wid = tid >> 5, lane = tid & 31;
    const int wy = wid >> 1, wx = wid & 1;   // 4 row-groups x 2 col-groups

    // map blockIdx -> (bi, group of 4 column tiles)
    int id = blockIdx.x, bi = 0;
    for (; bi < ROWBLKS; bi++) {
        int cnt = (ROWBLKS - bi + 3) >> 2;
        if (id < cnt) break;
        id -= cnt;
    }
    const int bj0 = bi + 4 * id;
    const int nt = min(4, ROWBLKS - bj0);
    const int rowbase = bi * 128;

    // ---- prologue: A stripe (hi|lo), B tile 0, meta 0 ----
    #pragma unroll
    for (int i = 0; i < 16; i++) {
        int idx = tid + i * 256;
        int r = idx >> 5, c = idx & 31;
        CP_ASYNC16(sb + OFF_A + r * PSTRB + c * 16,
                   g_P + (size_t)(rowbase + r) * 256 + c * 8);
    }
    CP_COMMIT();
    {
        const int cb = bj0 * 128;
        #pragma unroll
        for (int i = 0; i < 16; i++) {
            int idx = tid + i * 256;
            int r = idx >> 5, c = idx & 31;
            CP_ASYNC16(sb + OFF_B0 + r * PSTRB + c * 16,
                       g_P + (size_t)(cb + r) * 256 + c * 8);
        }
        if (tid < 64)
            CP_ASYNC16(sb + OFF_MT0 + tid * 16, (const char*)(g_meta + cb) + tid * 16);
        CP_COMMIT();
    }

    // this thread's 4 anchor rows: 32*wy + 16*mb + (lane>>2) + 8*{0,1}
    int   trow[4];
    int   rl[4];
    float sqa[4], hp[4], hn[4];
    #pragma unroll
    for (int mb = 0; mb < 2; mb++) {
        #pragma unroll
        for (int h = 0; h < 2; h++) {
            int r = rowbase + 32 * wy + 16 * mb + 8 * h + (lane >> 2);
            float2 m = g_meta[r];
            trow[2 * mb + h] = r;
            rl[2 * mb + h] = __float_as_int(m.y);
            sqa[2 * mb + h] = m.x;
            hp[2 * mb + h] = -1e30f;
            hn[2 * mb + h] = 1e30f;
        }
    }

    const uint32_t aAddr = sb + OFF_A
        + (uint32_t)(32 * wy + 8 * ((lane >> 3) & 1) + (lane & 7)) * PSTRB
        + (uint32_t)(8 * (lane >> 4)) * 2;
    const uint32_t bColOff = (uint32_t)(64 * wx) * PSTRB
        + (uint32_t)(8 * (lane >> 4) + (lane & 7)) * PSTRB
        + (uint32_t)(8 * ((lane >> 3) & 1)) * 2;

    float* sCBP = (float*)(smem + OFF_CBP);
    float* sCBN = (float*)(smem + OFF_CBN);

    for (int t = 0; t < nt; t++) {
        CP_WAIT0();
        __syncthreads();     // loads visible; colbuf from t-1 fully consumed

        if (t + 1 < nt) {    // prefetch next B + meta
            const uint32_t dstB = sb + (((t + 1) & 1) ? OFF_B1 : OFF_B0);
            const int cb = (bj0 + t + 1) * 128;
            #pragma unroll
            for (int i = 0; i < 16; i++) {
                int idx = tid + i * 256;
                int r = idx >> 5, c = idx & 31;
                CP_ASYNC16(dstB + r * PSTRB + c * 16,
                           g_P + (size_t)(cb + r) * 256 + c * 8);
            }
            if (tid < 64)
                CP_ASYNC16(sb + (((t + 1) & 1) ? OFF_MT1 : OFF_MT0) + tid * 16,
                           (const char*)(g_meta + cb) + tid * 16);
            CP_COMMIT();
        }

        const uint32_t bBase = sb + ((t & 1) ? OFF_B1 : OFF_B0) + bColOff;

        float acc[16][4];    // [mb*8+nb][e] : 32 rows x 64 cols per warp
        #pragma unroll
        for (int f = 0; f < 16; f++)
            #pragma unroll
            for (int e = 0; e < 4; e++) acc[f][e] = 0.0f;

        #pragma unroll
        for (int ks = 0; ks < 8; ks++) {
            uint32_t Ah[2][4], Al[2][4], Bf[4][4];
            #pragma unroll
            for (int mb = 0; mb < 2; mb++) {
                LDSM4(Ah[mb][0], Ah[mb][1], Ah[mb][2], Ah[mb][3],
                      aAddr + (uint32_t)(16 * mb * PSTRB) + (uint32_t)(32 * ks));
                LDSM4(Al[mb][0], Al[mb][1], Al[mb][2], Al[mb][3],
                      aAddr + (uint32_t)(16 * mb * PSTRB) + 256u + (uint32_t)(32 * ks));
            }
            #pragma unroll
            for (int nb = 0; nb < 4; nb++)
                LDSM4(Bf[nb][0], Bf[nb][1], Bf[nb][2], Bf[nb][3],
                      bBase + (uint32_t)(nb * 16 * PSTRB) + (uint32_t)(32 * ks));
            // hi_A * hi_B and lo_A * hi_B
            #pragma unroll
            for (int mb = 0; mb < 2; mb++)
                #pragma unroll
                for (int nb = 0; nb < 4; nb++) {
                    MMA16816(acc[mb * 8 + 2 * nb],
                             Ah[mb][0], Ah[mb][1], Ah[mb][2], Ah[mb][3],
                             Bf[nb][0], Bf[nb][1]);
                    MMA16816(acc[mb * 8 + 2 * nb + 1],
                             Ah[mb][0], Ah[mb][1], Ah[mb][2], Ah[mb][3],
                             Bf[nb][2], Bf[nb][3]);
                }
            #pragma unroll
            for (int mb = 0; mb < 2; mb++)
                #pragma unroll
                for (int nb = 0; nb < 4; nb++) {
                    MMA16816(acc[mb * 8 + 2 * nb],
                             Al[mb][0], Al[mb][1], Al[mb][2], Al[mb][3],
                             Bf[nb][0], Bf[nb][1]);
                    MMA16816(acc[mb * 8 + 2 * nb + 1],
                             Al[mb][0], Al[mb][1], Al[mb][2], Al[mb][3],
                             Bf[nb][2], Bf[nb][3]);
                }
            // reload B with lo fragments, hi_A * lo_B
            #pragma unroll
            for (int nb = 0; nb < 4; nb++)
                LDSM4(Bf[nb][0], Bf[nb][1], Bf[nb][2], Bf[nb][3],
                      bBase + (uint32_t)(nb * 16 * PSTRB) + 256u + (uint32_t)(32 * ks));
            #pragma unroll
            for (int mb = 0; mb < 2; mb++)
                #pragma unroll
                for (int nb = 0; nb < 4; nb++) {
                    MMA16816(acc[mb * 8 + 2 * nb],
                             Ah[mb][0], Ah[mb][1], Ah[mb][2], Ah[mb][3],
                             Bf[nb][0], Bf[nb][1]);
                    MMA16816(acc[mb * 8 + 2 * nb + 1],
                             Ah[mb][0], Ah[mb][1], Ah[mb][2], Ah[mb][3],
                             Bf[nb][2], Bf[nb][3]);
                }
        }

        // ---- epilogue: row folds in regs; column partials -> smem colbuf ----
        {
            const float2* mp = (const float2*)(smem + ((t & 1) ? OFF_MT1 : OFF_MT0));
            const int cgb = (bj0 + t) * 128;
            #pragma unroll
            for (int nb = 0; nb < 8; nb++) {
                const int cl = 64 * wx + 8 * nb + 2 * (lane & 3);
                const float2 m0 = mp[cl];
                const float2 m1 = mp[cl + 1];
                const int c0 = cgb + cl, c1 = c0 + 1;
                const int l0 = __float_as_int(m0.y);
                const int l1 = __float_as_int(m1.y);
                float cp0 = -1e30f, cp1 = -1e30f, cn0 = 1e30f, cn1 = 1e30f;
                #pragma unroll
                for (int mb = 0; mb < 2; mb++) {
                    const int fi = mb * 8 + nb;
                    const int r0 = trow[2 * mb], r1 = trow[2 * mb + 1];
                    const int la = rl[2 * mb], lb = rl[2 * mb + 1];
                    const float v00 = fmaf(-2.0f, acc[fi][0], m0.x);
                    const float v01 = fmaf(-2.0f, acc[fi][1], m1.x);
                    const float v10 = fmaf(-2.0f, acc[fi][2], m0.x);
                    const float v11 = fmaf(-2.0f, acc[fi][3], m1.x);
                    const float w00 = fmaf(-2.0f, acc[fi][0], sqa[2 * mb]);
                    const float w01 = fmaf(-2.0f, acc[fi][1], sqa[2 * mb]);
                    const float w10 = fmaf(-2.0f, acc[fi][2], sqa[2 * mb + 1]);
                    const float w11 = fmaf(-2.0f, acc[fi][3], sqa[2 * mb + 1]);
                    const bool s00 = (l0 == la), s01 = (l1 == la);
                    const bool s10 = (l0 == lb), s11 = (l1 == lb);
                    if (s00) { if (c0 != r0) hp[2*mb]   = fmaxf(hp[2*mb],   v00); }
                    else hn[2*mb]   = fminf(hn[2*mb],   v00);
                    if (s01) { if (c1 != r0) hp[2*mb]   = fmaxf(hp[2*mb],   v01); }
                    else hn[2*mb]   = fminf(hn[2*mb],   v01);
                    if (s10) { if (c0 != r1) hp[2*mb+1] = fmaxf(hp[2*mb+1], v10); }
                    else hn[2*mb+1] = fminf(hn[2*mb+1], v10);
                    if (s11) { if (c1 != r1) hp[2*mb+1] = fmaxf(hp[2*mb+1], v11); }
                    else hn[2*mb+1] = fminf(hn[2*mb+1], v11);
                    cp0 = fmaxf(cp0, fmaxf((s00 && c0 != r0) ? w00 : -1e30f,
                                           (s10 && c0 != r1) ? w10 : -1e30f));
                    cp1 = fmaxf(cp1, fmaxf((s01 && c1 != r0) ? w01 : -1e30f,
                                           (s11 && c1 != r1) ? w11 : -1e30f));
                    cn0 = fminf(cn0, fminf(s00 ? 1e30f : w00, s10 ? 1e30f : w10));
                    cn1 = fminf(cn1, fminf(s01 ? 1e30f : w01, s11 ? 1e30f : w11));
                }
                #pragma unroll
                for (int o = 4; o < 32; o <<= 1) {
                    cp0 = fmaxf(cp0, __shfl_xor_sync(0xFFFFFFFFu, cp0, o));
                    cp1 = fmaxf(cp1, __shfl_xor_sync(0xFFFFFFFFu, cp1, o));
                    cn0 = fminf(cn0, __shfl_xor_sync(0xFFFFFFFFu, cn0, o));
                    cn1 = fminf(cn1, __shfl_xor_sync(0xFFFFFFFFu, cn1, o));
                }
                if (lane < 4) {            // disjoint addresses: plain stores
                    sCBP[wy * 128 + cl]     = cp0;
                    sCBP[wy * 128 + cl + 1] = cp1;
                    sCBN[wy * 128 + cl]     = cn0;
                    sCBN[wy * 128 + cl + 1] = cn1;
                }
            }
        }
        __syncthreads();
        if (tid < 128) {     // fold 4 row-groups, one global RED pair per column
            const int c = (bj0 + t) * 128 + tid;
            float p = sCBP[tid], q = sCBN[tid];
            #pragma unroll
            for (int w = 1; w < 4; w++) {
                p = fmaxf(p, sCBP[w * 128 + tid]);
                q = fminf(q, sCBN[w * 128 + tid]);
            }
            if (p > -1e29f) atomicMax(&g_apos[c], enc(p));
            if (q <  1e29f) atomicMin(&g_aneg[c], enc(q));
        }
    }

    // row folds -> global (fold the 4 lanes of each row quad first)
    #pragma unroll
    for (int o = 1; o < 4; o <<= 1) {
        #pragma unroll
        for (int i = 0; i < 4; i++) {
            hp[i] = fmaxf(hp[i], __shfl_xor_sync(0xFFFFFFFFu, hp[i], o));
            hn[i] = fminf(hn[i], __shfl_xor_sync(0xFFFFFFFFu, hn[i], o));
        }
    }
    if ((lane & 3) == 0) {
        #pragma unroll
        for (int i = 0; i < 4; i++) {
            if (hp[i] > -1e29f) atomicMax(&g_apos[trow[i]], enc(hp[i]));
            if (hn[i] <  1e29f) atomicMin(&g_aneg[trow[i]], enc(hn[i]));
        }
    }
}

// ---------------- finalize ----------------
__global__ void finalize_kernel(float* __restrict__ out, int n) {
    __shared__ float s_sum[32], s_cnt[32];
    float sum = 0.0f, cnt = 0.0f;
    for (int r = threadIdx.x; r < n; r += blockDim.x) {
        float hp = dec(g_apos[r]);
        float hn = dec(g_aneg[r]);
        if (hp > -1e29f && hn < 1e29f) {
            float sqa = g_meta[r].x;
            float dp = sqrtf(fmaxf(sqa + hp, 0.0f));
            float dn = sqrtf(fmaxf(sqa + hn, 0.0f));
            sum += fmaxf(dp - dn + 0.3f, 0.0f);
            cnt += 1.0f;
        }
    }
    int lane = threadIdx.x & 31, wid = threadIdx.x >> 5;
    #pragma unroll
    for (int o = 16; o > 0; o >>= 1) {
        sum += __shfl_xor_sync(0xFFFFFFFFu, sum, o);
        cnt += __shfl_xor_sync(0xFFFFFFFFu, cnt, o);
    }
    if (lane == 0) { s_sum[wid] = sum; s_cnt[wid] = cnt; }
    __syncthreads();
    if (threadIdx.x < 32) {
        int nw = blockDim.x >> 5;
        sum = (threadIdx.x < nw) ? s_sum[threadIdx.x] : 0.0f;
        cnt = (threadIdx.x < nw) ? s_cnt[threadIdx.x] : 0.0f;
        #pragma unroll
        for (int o = 16; o > 0; o >>= 1) {
            sum += __shfl_xor_sync(0xFFFFFFFFu, sum, o);
            cnt += __shfl_xor_sync(0xFFFFFFFFu, cnt, o);
        }
        if (threadIdx.x == 0) out[0] = (cnt > 0.0f) ? (sum / cnt) : 0.0f;
    }
}

// ---------------- launch (5 kernels: main is launch index 3) ----------------
extern "C" void kernel_launch(void* const* d_in, const int* in_sizes, int n_in,
                              void* d_out, int out_size) {
    const float* emb = (const float*)d_in[0];
    const int* labw = (const int*)d_in[1];
    int n = in_sizes[0] / DDIM;   // 8192

    cudaFuncSetAttribute(hmma_sym_kernel,
                         cudaFuncAttributeMaxDynamicSharedMemorySize, SMEM_TOTAL);

    detect_kernel<<<1, 1024>>>(labw, n);
    prep_meta_kernel<<<(n + 7) / 8, 256>>>(labw, (const float4*)emb, n);
    pack_kernel<<<(n * 16) / 256, 256>>>(emb);
    hmma_sym_kernel<<<GRID_MAIN, 256, SMEM_TOTAL>>>();
    finalize_kernel<<<1, 1024>>>((float*)d_out, n);
}

// round 15
// speedup vs baseline: 4.8787x; 1.0428x over previous
#include <cuda_runtime.h>
#include <cuda_fp16.h>
#include <cstdint>

// BatchHardTripletLoss via fp16 hi/lo-split HMMA with Gram-symmetry halving.
// Upper-triangle 128x128 tiles; folded row-wise and column-wise.
// 512 threads/CTA, 16 warps as 4x4 grid, warp tile 32x32
// (8 LDSM.x4 per 24 MMAs per k-step; acc=32 regs -> no spills, 4 warps/SMSP).

#define NROWS  8192
#define DDIM   128
#define ROWBLKS 64
#define GRID_MAIN 544     // sum_{bi} ceil((64-bi)/4)
#define PSTRB   528       // smem row stride bytes (264 halfs)

// ---------------- device scratch ----------------
__device__ __align__(16) __half g_P[NROWS * 256];   // [row][0:128]=hi, [128:256]=lo
__device__ float2 g_meta[NROWS];                    // (sqnorm, label bits)
__device__ int    g_is64;
__device__ unsigned g_apos[NROWS];                  // encoded hardest-pos (max)
__device__ unsigned g_aneg[NROWS];                  // encoded hardest-neg (min)

// ---------------- helpers ----------------
__device__ __forceinline__ uint32_t smem_u32(const void* p) {
    uint32_t a;
    asm("{ .reg .u64 t; cvta.to.shared.u64 t, %1; cvt.u32.u64 %0, t; }" : "=r"(a) : "l"(p));
    return a;
}
__device__ __forceinline__ unsigned enc(float x) {
    int i = __float_as_int(x);
    return (i < 0) ? (unsigned)(~i) : ((unsigned)i | 0x80000000u);
}
__device__ __forceinline__ float dec(unsigned u) {
    int i = (u & 0x80000000u) ? (int)(u ^ 0x80000000u) : ~(int)u;
    return __int_as_float(i);
}
#define CP_ASYNC16(dst, src) \
    asm volatile("cp.async.cg.shared.global [%0], [%1], 16;" :: "r"(dst), "l"(src))
#define CP_COMMIT() asm volatile("cp.async.commit_group;" ::: "memory")
#define CP_WAIT0()  asm volatile("cp.async.wait_group 0;" ::: "memory")
#define LDSM4(R0, R1, R2, R3, ADDR) \
    asm volatile("ldmatrix.sync.aligned.m8n8.x4.shared.b16 {%0,%1,%2,%3}, [%4];" \
        : "=r"(R0), "=r"(R1), "=r"(R2), "=r"(R3) : "r"(ADDR))
#define MMA16816(C, A0, A1, A2, A3, B0, B1) \
    asm volatile("mma.sync.aligned.m16n8k16.row.col.f32.f16.f16.f32 " \
        "{%0,%1,%2,%3}, {%4,%5,%6,%7}, {%8,%9}, {%0,%1,%2,%3};" \
        : "+f"((C)[0]), "+f"((C)[1]), "+f"((C)[2]), "+f"((C)[3]) \
        : "r"(A0), "r"(A1), "r"(A2), "r"(A3), "r"(B0), "r"(B1))

// ---------------- prep kernels ----------------
__global__ void detect_kernel(const int* __restrict__ words, int n) {
    __shared__ int any_odd;
    if (threadIdx.x == 0) any_odd = 0;
    __syncthreads();
    int local = 0;
    for (int i = 1 + 2 * (int)threadIdx.x; i < n; i += 2 * blockDim.x) local |= words[i];
    if (local) atomicOr(&any_odd, 1);
    __syncthreads();
    if (threadIdx.x == 0) g_is64 = (any_odd == 0) ? 1 : 0;
}
__global__ void prep_meta_kernel(const int* __restrict__ words,
                                 const float4* __restrict__ emb4, int n) {
    int row  = blockIdx.x * 8 + (threadIdx.x >> 5);
    int lane = threadIdx.x & 31;
    if (row < n) {
        float4 v = emb4[row * 32 + lane];
        float s = v.x * v.x + v.y * v.y + v.z * v.z + v.w * v.w;
        #pragma unroll
        for (int o = 16; o > 0; o >>= 1) s += __shfl_xor_sync(0xFFFFFFFFu, s, o);
        if (lane == 0) {
            int lab = words[g_is64 ? (2 * row) : row];
            g_meta[row] = make_float2(s, __int_as_float(lab));
            g_apos[row] = enc(-1e30f);
            g_aneg[row] = enc(1e30f);
        }
    }
}
__global__ void pack_kernel(const float* __restrict__ emb) {
    int c = blockIdx.x * blockDim.x + threadIdx.x;
    int row = c >> 4;
    int k8 = (c & 15) * 8;
    const float4* p = (const float4*)(emb + row * DDIM + k8);
    float4 v0 = p[0], v1 = p[1];
    float v[8] = {v0.x, v0.y, v0.z, v0.w, v1.x, v1.y, v1.z, v1.w};
    __half hi[8], lo[8];
    #pragma unroll
    for (int i = 0; i < 8; i++) {
        hi[i] = __float2half_rn(v[i]);
        lo[i] = __float2half_rn(v[i] - __half2float(hi[i]));
    }
    *(uint4*)(g_P + row * 256 + k8)       = *(const uint4*)hi;
    *(uint4*)(g_P + row * 256 + 128 + k8) = *(const uint4*)lo;
}

// ---------------- main symmetric HMMA kernel ----------------
#define OFF_A     0
#define OFF_B0    67584
#define OFF_B1    135168
#define OFF_MT0   202752
#define OFF_MT1   203776
#define OFF_CBP   204800    // colbuf pos: 4 x 128 floats
#define OFF_CBN   206848    // colbuf neg: 4 x 128 floats
#define SMEM_TOTAL 208896

__global__ void __launch_bounds__(512, 1) hmma_sym_kernel() {
    extern __shared__ char smem[];
    const uint32_t sb = smem_u32(smem);
    const int tid = threadIdx.x, wid = tid >> 5, lane = tid & 31;
    const int wy = wid >> 2, wx = wid & 3;   // 4 row-groups x 4 col-groups

    // map blockIdx -> (bi, group of 4 column tiles)
    int id = blockIdx.x, bi = 0;
    for (; bi < ROWBLKS; bi++) {
        int cnt = (ROWBLKS - bi + 3) >> 2;
        if (id < cnt) break;
        id -= cnt;
    }
    const int bj0 = bi + 4 * id;
    const int nt = min(4, ROWBLKS - bj0);
    const int rowbase = bi * 128;

    // ---- prologue: A stripe (hi|lo), B tile 0, meta 0 ----
    #pragma unroll
    for (int i = 0; i < 8; i++) {
        int idx = tid + i * 512;
        int r = idx >> 5, c = idx & 31;
        CP_ASYNC16(sb + OFF_A + r * PSTRB + c * 16,
                   g_P + (size_t)(rowbase + r) * 256 + c * 8);
    }
    CP_COMMIT();
    {
        const int cb = bj0 * 128;
        #pragma unroll
        for (int i = 0; i < 8; i++) {
            int idx = tid + i * 512;
            int r = idx >> 5, c = idx & 31;
            CP_ASYNC16(sb + OFF_B0 + r * PSTRB + c * 16,
                       g_P + (size_t)(cb + r) * 256 + c * 8);
        }
        if (tid < 64)
            CP_ASYNC16(sb + OFF_MT0 + tid * 16, (const char*)(g_meta + cb) + tid * 16);
        CP_COMMIT();
    }

    // this thread's 4 anchor rows: 32*wy + 16*mb + 8*h + (lane>>2)
    int   trow[4];
    int   rl[4];
    float sqa[4], hp[4], hn[4];
    #pragma unroll
    for (int mb = 0; mb < 2; mb++) {
        #pragma unroll
        for (int h = 0; h < 2; h++) {
            int r = rowbase + 32 * wy + 16 * mb + 8 * h + (lane >> 2);
            float2 m = g_meta[r];
            trow[2 * mb + h] = r;
            rl[2 * mb + h] = __float_as_int(m.y);
            sqa[2 * mb + h] = m.x;
            hp[2 * mb + h] = -1e30f;
            hn[2 * mb + h] = 1e30f;
        }
    }

    const uint32_t aAddr = sb + OFF_A
        + (uint32_t)(32 * wy + 8 * ((lane >> 3) & 1) + (lane & 7)) * PSTRB
        + (uint32_t)(8 * (lane >> 4)) * 2;
    const uint32_t bColOff = (uint32_t)(32 * wx) * PSTRB
        + (uint32_t)(8 * (lane >> 4) + (lane & 7)) * PSTRB
        + (uint32_t)(8 * ((lane >> 3) & 1)) * 2;

    float* sCBP = (float*)(smem + OFF_CBP);
    float* sCBN = (float*)(smem + OFF_CBN);

    for (int t = 0; t < nt; t++) {
        CP_WAIT0();
        __syncthreads();     // loads visible; colbuf from t-1 fully consumed

        if (t + 1 < nt) {    // prefetch next B + meta
            const uint32_t dstB = sb + (((t + 1) & 1) ? OFF_B1 : OFF_B0);
            const int cb = (bj0 + t + 1) * 128;
            #pragma unroll
            for (int i = 0; i < 8; i++) {
                int idx = tid + i * 512;
                int r = idx >> 5, c = idx & 31;
                CP_ASYNC16(dstB + r * PSTRB + c * 16,
                           g_P + (size_t)(cb + r) * 256 + c * 8);
            }
            if (tid < 64)
                CP_ASYNC16(sb + (((t + 1) & 1) ? OFF_MT1 : OFF_MT0) + tid * 16,
                           (const char*)(g_meta + cb) + tid * 16);
            CP_COMMIT();
        }

        const uint32_t bBase = sb + ((t & 1) ? OFF_B1 : OFF_B0) + bColOff;

        float acc[8][4];     // [mb*4 + n8][e] : 32 rows x 32 cols per warp
        #pragma unroll
        for (int f = 0; f < 8; f++)
            #pragma unroll
            for (int e = 0; e < 4; e++) acc[f][e] = 0.0f;

        #pragma unroll
        for (int ks = 0; ks < 8; ks++) {
            uint32_t Ah[2][4], Al[2][4], Bf[2][4];
            #pragma unroll
            for (int mb = 0; mb < 2; mb++) {
                LDSM4(Ah[mb][0], Ah[mb][1], Ah[mb][2], Ah[mb][3],
                      aAddr + (uint32_t)(16 * mb * PSTRB) + (uint32_t)(32 * ks));
                LDSM4(Al[mb][0], Al[mb][1], Al[mb][2], Al[mb][3],
                      aAddr + (uint32_t)(16 * mb * PSTRB) + 256u + (uint32_t)(32 * ks));
            }
            #pragma unroll
            for (int nb = 0; nb < 2; nb++)
                LDSM4(Bf[nb][0], Bf[nb][1], Bf[nb][2], Bf[nb][3],
                      bBase + (uint32_t)(nb * 16 * PSTRB) + (uint32_t)(32 * ks));
            // hi_A * hi_B and lo_A * hi_B
            #pragma unroll
            for (int mb = 0; mb < 2; mb++)
                #pragma unroll
                for (int nb = 0; nb < 2; nb++) {
                    MMA16816(acc[mb * 4 + 2 * nb],
                             Ah[mb][0], Ah[mb][1], Ah[mb][2], Ah[mb][3],
                             Bf[nb][0], Bf[nb][1]);
                    MMA16816(acc[mb * 4 + 2 * nb + 1],
                             Ah[mb][0], Ah[mb][1], Ah[mb][2], Ah[mb][3],
                             Bf[nb][2], Bf[nb][3]);
                }
            #pragma unroll
            for (int mb = 0; mb < 2; mb++)
                #pragma unroll
                for (int nb = 0; nb < 2; nb++) {
                    MMA16816(acc[mb * 4 + 2 * nb],
                             Al[mb][0], Al[mb][1], Al[mb][2], Al[mb][3],
                             Bf[nb][0], Bf[nb][1]);
                    MMA16816(acc[mb * 4 + 2 * nb + 1],
                             Al[mb][0], Al[mb][1], Al[mb][2], Al[mb][3],
                             Bf[nb][2], Bf[nb][3]);
                }
            // reload B with lo fragments, hi_A * lo_B
            #pragma unroll
            for (int nb = 0; nb < 2; nb++)
                LDSM4(Bf[nb][0], Bf[nb][1], Bf[nb][2], Bf[nb][3],
                      bBase + (uint32_t)(nb * 16 * PSTRB) + 256u + (uint32_t)(32 * ks));
            #pragma unroll
            for (int mb = 0; mb < 2; mb++)
                #pragma unroll
                for (int nb = 0; nb < 2; nb++) {
                    MMA16816(acc[mb * 4 + 2 * nb],
                             Ah[mb][0], Ah[mb][1], Ah[mb][2], Ah[mb][3],
                             Bf[nb][0], Bf[nb][1]);
                    MMA16816(acc[mb * 4 + 2 * nb + 1],
                             Ah[mb][0], Ah[mb][1], Ah[mb][2], Ah[mb][3],
                             Bf[nb][2], Bf[nb][3]);
                }
        }

        // ---- epilogue: row folds in regs; column partials -> smem colbuf ----
        {
            const float2* mp = (const float2*)(smem + ((t & 1) ? OFF_MT1 : OFF_MT0));
            const int cgb = (bj0 + t) * 128;
            #pragma unroll
            for (int j = 0; j < 4; j++) {       // n8 blocks within warp's 32 cols
                const int cl = 32 * wx + 8 * j + 2 * (lane & 3);
                const float2 m0 = mp[cl];
                const float2 m1 = mp[cl + 1];
                const int c0 = cgb + cl, c1 = c0 + 1;
                const int l0 = __float_as_int(m0.y);
                const int l1 = __float_as_int(m1.y);
                float cp0 = -1e30f, cp1 = -1e30f, cn0 = 1e30f, cn1 = 1e30f;
                #pragma unroll
                for (int mb = 0; mb < 2; mb++) {
                    const int fi = mb * 4 + j;
                    const int r0 = trow[2 * mb], r1 = trow[2 * mb + 1];
                    const int la = rl[2 * mb], lb = rl[2 * mb + 1];
                    const float v00 = fmaf(-2.0f, acc[fi][0], m0.x);
                    const float v01 = fmaf(-2.0f, acc[fi][1], m1.x);
                    const float v10 = fmaf(-2.0f, acc[fi][2], m0.x);
                    const float v11 = fmaf(-2.0f, acc[fi][3], m1.x);
                    const float w00 = fmaf(-2.0f, acc[fi][0], sqa[2 * mb]);
                    const float w01 = fmaf(-2.0f, acc[fi][1], sqa[2 * mb]);
                    const float w10 = fmaf(-2.0f, acc[fi][2], sqa[2 * mb + 1]);
                    const float w11 = fmaf(-2.0f, acc[fi][3], sqa[2 * mb + 1]);
                    const bool s00 = (l0 == la), s01 = (l1 == la);
                    const bool s10 = (l0 == lb), s11 = (l1 == lb);
                    if (s00) { if (c0 != r0) hp[2*mb]   = fmaxf(hp[2*mb],   v00); }
                    else hn[2*mb]   = fminf(hn[2*mb],   v00);
                    if (s01) { if (c1 != r0) hp[2*mb]   = fmaxf(hp[2*mb],   v01); }
                    else hn[2*mb]   = fminf(hn[2*mb],   v01);
                    if (s10) { if (c0 != r1) hp[2*mb+1] = fmaxf(hp[2*mb+1], v10); }
                    else hn[2*mb+1] = fminf(hn[2*mb+1], v10);
                    if (s11) { if (c1 != r1) hp[2*mb+1] = fmaxf(hp[2*mb+1], v11); }
                    else hn[2*mb+1] = fminf(hn[2*mb+1], v11);
                    cp0 = fmaxf(cp0, fmaxf((s00 && c0 != r0) ? w00 : -1e30f,
                                           (s10 && c0 != r1) ? w10 : -1e30f));
                    cp1 = fmaxf(cp1, fmaxf((s01 && c1 != r0) ? w01 : -1e30f,
                                           (s11 && c1 != r1) ? w11 : -1e30f));
                    cn0 = fminf(cn0, fminf(s00 ? 1e30f : w00, s10 ? 1e30f : w10));
                    cn1 = fminf(cn1, fminf(s01 ? 1e30f : w01, s11 ? 1e30f : w11));
                }
                #pragma unroll
                for (int o = 4; o < 32; o <<= 1) {
                    cp0 = fmaxf(cp0, __shfl_xor_sync(0xFFFFFFFFu, cp0, o));
                    cp1 = fmaxf(cp1, __shfl_xor_sync(0xFFFFFFFFu, cp1, o));
                    cn0 = fminf(cn0, __shfl_xor_sync(0xFFFFFFFFu, cn0, o));
                    cn1 = fminf(cn1, __shfl_xor_sync(0xFFFFFFFFu, cn1, o));
                }
                if (lane < 4) {            // disjoint addresses: plain stores
                    sCBP[wy * 128 + cl]     = cp0;
                    sCBP[wy * 128 + cl + 1] = cp1;
                    sCBN[wy * 128 + cl]     = cn0;
                    sCBN[wy * 128 + cl + 1] = cn1;
                }
            }
        }
        __syncthreads();
        if (tid < 128) {     // fold 4 row-groups, one global RED pair per column
            const int c = (bj0 + t) * 128 + tid;
            float p = sCBP[tid], q = sCBN[tid];
            #pragma unroll
            for (int w = 1; w < 4; w++) {
                p = fmaxf(p, sCBP[w * 128 + tid]);
                q = fminf(q, sCBN[w * 128 + tid]);
            }
            if (p > -1e29f) atomicMax(&g_apos[c], enc(p));
            if (q <  1e29f) atomicMin(&g_aneg[c], enc(q));
        }
    }

    // row folds -> global (fold the 4 lanes of each row quad first)
    #pragma unroll
    for (int o = 1; o < 4; o <<= 1) {
        #pragma unroll
        for (int i = 0; i < 4; i++) {
            hp[i] = fmaxf(hp[i], __shfl_xor_sync(0xFFFFFFFFu, hp[i], o));
            hn[i] = fminf(hn[i], __shfl_xor_sync(0xFFFFFFFFu, hn[i], o));
        }
    }
    if ((lane & 3) == 0) {
        #pragma unroll
        for (int i = 0; i < 4; i++) {
            if (hp[i] > -1e29f) atomicMax(&g_apos[trow[i]], enc(hp[i]));
            if (hn[i] <  1e29f) atomicMin(&g_aneg[trow[i]], enc(hn[i]));
        }
    }
}

// ---------------- finalize ----------------
__global__ void finalize_kernel(float* __restrict__ out, int n) {
    __shared__ float s_sum[32], s_cnt[32];
    float sum = 0.0f, cnt = 0.0f;
    for (int r = threadIdx.x; r < n; r += blockDim.x) {
        float hp = dec(g_apos[r]);
        float hn = dec(g_aneg[r]);
        if (hp > -1e29f && hn < 1e29f) {
            float sqa = g_meta[r].x;
            float dp = sqrtf(fmaxf(sqa + hp, 0.0f));
            float dn = sqrtf(fmaxf(sqa + hn, 0.0f));
            sum += fmaxf(dp - dn + 0.3f, 0.0f);
            cnt += 1.0f;
        }
    }
    int lane = threadIdx.x & 31, wid = threadIdx.x >> 5;
    #pragma unroll
    for (int o = 16; o > 0; o >>= 1) {
        sum += __shfl_xor_sync(0xFFFFFFFFu, sum, o);
        cnt += __shfl_xor_sync(0xFFFFFFFFu, cnt, o);
    }
    if (lane == 0) { s_sum[wid] = sum; s_cnt[wid] = cnt; }
    __syncthreads();
    if (threadIdx.x < 32) {
        int nw = blockDim.x >> 5;
        sum = (threadIdx.x < nw) ? s_sum[threadIdx.x] : 0.0f;
        cnt = (threadIdx.x < nw) ? s_cnt[threadIdx.x] : 0.0f;
        #pragma unroll
        for (int o = 16; o > 0; o >>= 1) {
            sum += __shfl_xor_sync(0xFFFFFFFFu, sum, o);
            cnt += __shfl_xor_sync(0xFFFFFFFFu, cnt, o);
        }
        if (threadIdx.x == 0) out[0] = (cnt > 0.0f) ? (sum / cnt) : 0.0f;
    }
}

// ---------------- launch (5 kernels: main is launch index 3) ----------------
extern "C" void kernel_launch(void* const* d_in, const int* in_sizes, int n_in,
                              void* d_out, int out_size) {
    const float* emb = (const float*)d_in[0];
    const int* labw = (const int*)d_in[1];
    int n = in_sizes[0] / DDIM;   // 8192

    cudaFuncSetAttribute(hmma_sym_kernel,
                         cudaFuncAttributeMaxDynamicSharedMemorySize, SMEM_TOTAL);

    detect_kernel<<<1, 1024>>>(labw, n);
    prep_meta_kernel<<<(n + 7) / 8, 256>>>(labw, (const float4*)emb, n);
    pack_kernel<<<(n * 16) / 256, 256>>>(emb);
    hmma_sym_kernel<<<GRID_MAIN, 512, SMEM_TOTAL>>>();
    finalize_kernel<<<1, 1024>>>((float*)d_out, n);
}

// round 16
// speedup vs baseline: 5.1157x; 1.0486x over previous
#include <cuda_runtime.h>
#include <cuda_fp16.h>
#include <cstdint>

// BatchHardTripletLoss via fp16 hi/lo-split HMMA with Gram-symmetry halving.
// Upper-triangle 128x128 tiles; folded row-wise and column-wise.
// 512 threads/CTA, 16 warps as 4x4 grid, warp tile 32x32.
// Round 16: A-register-reuse k-step (6+2 LDSM, 24 MMA), deferred column fold
// with double-buffered colbuf (1 barrier/tile), fused prep (3 launches total).

#define NROWS  8192
#define DDIM   128
#define ROWBLKS 64
#define GRID_MAIN 544     // sum_{bi} ceil((64-bi)/4)
#define PSTRB   528       // smem row stride bytes (264 halfs)

// ---------------- device scratch ----------------
__device__ __align__(16) __half g_P[NROWS * 256];   // [row][0:128]=hi, [128:256]=lo
__device__ float2 g_meta[NROWS];                    // (sqnorm, label bits)
__device__ unsigned g_apos[NROWS];                  // encoded hardest-pos (max)
__device__ unsigned g_aneg[NROWS];                  // encoded hardest-neg (min)

// ---------------- helpers ----------------
__device__ __forceinline__ uint32_t smem_u32(const void* p) {
    uint32_t a;
    asm("{ .reg .u64 t; cvta.to.shared.u64 t, %1; cvt.u32.u64 %0, t; }" : "=r"(a) : "l"(p));
    return a;
}
__device__ __forceinline__ unsigned enc(float x) {
    int i = __float_as_int(x);
    return (i < 0) ? (unsigned)(~i) : ((unsigned)i | 0x80000000u);
}
__device__ __forceinline__ float dec(unsigned u) {
    int i = (u & 0x80000000u) ? (int)(u ^ 0x80000000u) : ~(int)u;
    return __int_as_float(i);
}
#define CP_ASYNC16(dst, src) \
    asm volatile("cp.async.cg.shared.global [%0], [%1], 16;" :: "r"(dst), "l"(src))
#define CP_COMMIT() asm volatile("cp.async.commit_group;" ::: "memory")
#define CP_WAIT0()  asm volatile("cp.async.wait_group 0;" ::: "memory")
#define LDSM4(R0, R1, R2, R3, ADDR) \
    asm volatile("ldmatrix.sync.aligned.m8n8.x4.shared.b16 {%0,%1,%2,%3}, [%4];" \
        : "=r"(R0), "=r"(R1), "=r"(R2), "=r"(R3) : "r"(ADDR))
#define MMA16816(C, A0, A1, A2, A3, B0, B1) \
    asm volatile("mma.sync.aligned.m16n8k16.row.col.f32.f16.f16.f32 " \
        "{%0,%1,%2,%3}, {%4,%5,%6,%7}, {%8,%9}, {%0,%1,%2,%3};" \
        : "+f"((C)[0]), "+f"((C)[1]), "+f"((C)[2]), "+f"((C)[3]) \
        : "r"(A0), "r"(A1), "r"(A2), "r"(A3), "r"(B0), "r"(B1))

// ---------------- fused prep: detect + labels + sqnorm + init + hi/lo pack ----
// One block = 16 rows (256 threads, 16 threads per row).
__global__ void pack_meta_kernel(const int* __restrict__ words,
                                 const float* __restrict__ emb, int n) {
    __shared__ int s_odd;
    const int tid = threadIdx.x;
    if (tid == 0) s_odd = 0;
    __syncthreads();
    const int c = blockIdx.x * blockDim.x + tid;
    const int row = c >> 4;
    const int k8 = (c & 15) * 8;

    // int64-vs-int32 detection, sampled within the bounds of the smaller layout.
    // (If int32, odd words are labels of random rows -> nonzero w.h.p.)
    if ((c & 15) == 0) {
        if (words[2 * (row & (n / 2 - 1)) + 1]) atomicOr(&s_odd, 1);
    }

    const float4* p = (const float4*)(emb + row * DDIM + k8);
    float4 v0 = p[0], v1 = p[1];
    float v[8] = {v0.x, v0.y, v0.z, v0.w, v1.x, v1.y, v1.z, v1.w};
    __half hi[8], lo[8];
    float s = 0.0f;
    #pragma unroll
    for (int i = 0; i < 8; i++) {
        s = fmaf(v[i], v[i], s);
        hi[i] = __float2half_rn(v[i]);
        lo[i] = __float2half_rn(v[i] - __half2float(hi[i]));
    }
    // reduce sqnorm over the 16 threads sharing this row
    #pragma unroll
    for (int o = 1; o < 16; o <<= 1) s += __shfl_xor_sync(0xFFFFFFFFu, s, o);

    *(uint4*)(g_P + row * 256 + k8)       = *(const uint4*)hi;
    *(uint4*)(g_P + row * 256 + 128 + k8) = *(const uint4*)lo;

    __syncthreads();
    if ((c & 15) == 0) {
        const int is64 = (s_odd == 0);
        int lab = words[is64 ? (2 * row) : row];
        g_meta[row] = make_float2(s, __int_as_float(lab));
        g_apos[row] = enc(-1e30f);
        g_aneg[row] = enc(1e30f);
    }
}

// ---------------- main symmetric HMMA kernel ----------------
#define OFF_A     0
#define OFF_B0    67584
#define OFF_B1    135168
#define OFF_MT0   202752
#define OFF_MT1   203776
#define OFF_CB    204800    // 2 buffers x (512 pos + 512 neg floats) = 8KB
#define SMEM_TOTAL 212992

__global__ void __launch_bounds__(512, 1) hmma_sym_kernel() {
    extern __shared__ char smem[];
    const uint32_t sb = smem_u32(smem);
    const int tid = threadIdx.x, wid = tid >> 5, lane = tid & 31;
    const int wy = wid >> 2, wx = wid & 3;   // 4 row-groups x 4 col-groups

    // map blockIdx -> (bi, group of 4 column tiles)
    int id = blockIdx.x, bi = 0;
    for (; bi < ROWBLKS; bi++) {
        int cnt = (ROWBLKS - bi + 3) >> 2;
        if (id < cnt) break;
        id -= cnt;
    }
    const int bj0 = bi + 4 * id;
    const int nt = min(4, ROWBLKS - bj0);
    const int rowbase = bi * 128;

    // ---- prologue: A stripe (hi|lo), B tile 0, meta 0 ----
    #pragma unroll
    for (int i = 0; i < 8; i++) {
        int idx = tid + i * 512;
        int r = idx >> 5, cc = idx & 31;
        CP_ASYNC16(sb + OFF_A + r * PSTRB + cc * 16,
                   g_P + (size_t)(rowbase + r) * 256 + cc * 8);
    }
    CP_COMMIT();
    {
        const int cb = bj0 * 128;
        #pragma unroll
        for (int i = 0; i < 8; i++) {
            int idx = tid + i * 512;
            int r = idx >> 5, cc = idx & 31;
            CP_ASYNC16(sb + OFF_B0 + r * PSTRB + cc * 16,
                       g_P + (size_t)(cb + r) * 256 + cc * 8);
        }
        if (tid < 64)
            CP_ASYNC16(sb + OFF_MT0 + tid * 16, (const char*)(g_meta + cb) + tid * 16);
        CP_COMMIT();
    }

    // this thread's 4 anchor rows
    int   trow[4];
    int   rl[4];
    float sqa[4], hp[4], hn[4];
    #pragma unroll
    for (int mb = 0; mb < 2; mb++) {
        #pragma unroll
        for (int h = 0; h < 2; h++) {
            int r = rowbase + 32 * wy + 16 * mb + 8 * h + (lane >> 2);
            float2 m = g_meta[r];
            trow[2 * mb + h] = r;
            rl[2 * mb + h] = __float_as_int(m.y);
            sqa[2 * mb + h] = m.x;
            hp[2 * mb + h] = -1e30f;
            hn[2 * mb + h] = 1e30f;
        }
    }

    const uint32_t aAddr = sb + OFF_A
        + (uint32_t)(32 * wy + 8 * ((lane >> 3) & 1) + (lane & 7)) * PSTRB
        + (uint32_t)(8 * (lane >> 4)) * 2;
    const uint32_t bColOff = (uint32_t)(32 * wx) * PSTRB
        + (uint32_t)(8 * (lane >> 4) + (lane & 7)) * PSTRB
        + (uint32_t)(8 * ((lane >> 3) & 1)) * 2;

    for (int t = 0; t < nt; t++) {
        CP_WAIT0();
        __syncthreads();     // tile t resident; colbuf[(t-1)&1] writes visible

        // deferred column fold for tile t-1 (overlaps with prefetch + mainloop)
        if (t > 0 && tid < 128) {
            const float* fp = (const float*)(smem + OFF_CB + ((t - 1) & 1) * 4096);
            const float* fn = fp + 512;
            const int c = (bj0 + t - 1) * 128 + tid;
            float pv = fp[tid], qv = fn[tid];
            #pragma unroll
            for (int w = 1; w < 4; w++) {
                pv = fmaxf(pv, fp[w * 128 + tid]);
                qv = fminf(qv, fn[w * 128 + tid]);
            }
            if (pv > -1e29f) atomicMax(&g_apos[c], enc(pv));
            if (qv <  1e29f) atomicMin(&g_aneg[c], enc(qv));
        }

        if (t + 1 < nt) {    // prefetch next B + meta
            const uint32_t dstB = sb + (((t + 1) & 1) ? OFF_B1 : OFF_B0);
            const int cb = (bj0 + t + 1) * 128;
            #pragma unroll
            for (int i = 0; i < 8; i++) {
                int idx = tid + i * 512;
                int r = idx >> 5, cc = idx & 31;
                CP_ASYNC16(dstB + r * PSTRB + cc * 16,
                           g_P + (size_t)(cb + r) * 256 + cc * 8);
            }
            if (tid < 64)
                CP_ASYNC16(sb + (((t + 1) & 1) ? OFF_MT1 : OFF_MT0) + tid * 16,
                           (const char*)(g_meta + cb) + tid * 16);
            CP_COMMIT();
        }

        const uint32_t bBase = sb + ((t & 1) ? OFF_B1 : OFF_B0) + bColOff;

        float acc[8][4];     // 32 rows x 32 cols per warp
        #pragma unroll
        for (int f = 0; f < 8; f++)
            #pragma unroll
            for (int e = 0; e < 4; e++) acc[f][e] = 0.0f;

        #pragma unroll
        for (int ks = 0; ks < 8; ks++) {
            uint32_t Af[2][4], Bh[2][4], Bl[2][4];
            #pragma unroll
            for (int mb = 0; mb < 2; mb++)
                LDSM4(Af[mb][0], Af[mb][1], Af[mb][2], Af[mb][3],
                      aAddr + (uint32_t)(16 * mb * PSTRB) + (uint32_t)(32 * ks));
            #pragma unroll
            for (int nb = 0; nb < 2; nb++)
                LDSM4(Bh[nb][0], Bh[nb][1], Bh[nb][2], Bh[nb][3],
                      bBase + (uint32_t)(nb * 16 * PSTRB) + (uint32_t)(32 * ks));
            #pragma unroll
            for (int nb = 0; nb < 2; nb++)
                LDSM4(Bl[nb][0], Bl[nb][1], Bl[nb][2], Bl[nb][3],
                      bBase + (uint32_t)(nb * 16 * PSTRB) + 256u + (uint32_t)(32 * ks));
            // pass 1: hi_A * hi_B
            #pragma unroll
            for (int mb = 0; mb < 2; mb++)
                #pragma unroll
                for (int nb = 0; nb < 2; nb++) {
                    MMA16816(acc[mb * 4 + 2 * nb],
                             Af[mb][0], Af[mb][1], Af[mb][2], Af[mb][3],
                             Bh[nb][0], Bh[nb][1]);
                    MMA16816(acc[mb * 4 + 2 * nb + 1],
                             Af[mb][0], Af[mb][1], Af[mb][2], Af[mb][3],
                             Bh[nb][2], Bh[nb][3]);
                }
            // pass 2: hi_A * lo_B
            #pragma unroll
            for (int mb = 0; mb < 2; mb++)
                #pragma unroll
                for (int nb = 0; nb < 2; nb++) {
                    MMA16816(acc[mb * 4 + 2 * nb],
                             Af[mb][0], Af[mb][1], Af[mb][2], Af[mb][3],
                             Bl[nb][0], Bl[nb][1]);
                    MMA16816(acc[mb * 4 + 2 * nb + 1],
                             Af[mb][0], Af[mb][1], Af[mb][2], Af[mb][3],
                             Bl[nb][2], Bl[nb][3]);
                }
            // reload A regs with lo_A, pass 3: lo_A * hi_B
            #pragma unroll
            for (int mb = 0; mb < 2; mb++)
                LDSM4(Af[mb][0], Af[mb][1], Af[mb][2], Af[mb][3],
                      aAddr + (uint32_t)(16 * mb * PSTRB) + 256u + (uint32_t)(32 * ks));
            #pragma unroll
            for (int mb = 0; mb < 2; mb++)
                #pragma unroll
                for (int nb = 0; nb < 2; nb++) {
                    MMA16816(acc[mb * 4 + 2 * nb],
                             Af[mb][0], Af[mb][1], Af[mb][2], Af[mb][3],
                             Bh[nb][0], Bh[nb][1]);
                    MMA16816(acc[mb * 4 + 2 * nb + 1],
                             Af[mb][0], Af[mb][1], Af[mb][2], Af[mb][3],
                             Bh[nb][2], Bh[nb][3]);
                }
        }

        // ---- epilogue: row folds in regs; column partials -> colbuf[t&1] ----
        {
            const float2* mp = (const float2*)(smem + ((t & 1) ? OFF_MT1 : OFF_MT0));
            float* wp = (float*)(smem + OFF_CB + (t & 1) * 4096);
            const int cgb = (bj0 + t) * 128;
            #pragma unroll
            for (int j = 0; j < 4; j++) {
                const int cl = 32 * wx + 8 * j + 2 * (lane & 3);
                const float2 m0 = mp[cl];
                const float2 m1 = mp[cl + 1];
                const int c0 = cgb + cl, c1 = c0 + 1;
                const int l0 = __float_as_int(m0.y);
                const int l1 = __float_as_int(m1.y);
                float cp0 = -1e30f, cp1 = -1e30f, cn0 = 1e30f, cn1 = 1e30f;
                #pragma unroll
                for (int mb = 0; mb < 2; mb++) {
                    const int fi = mb * 4 + j;
                    const int r0 = trow[2 * mb], r1 = trow[2 * mb + 1];
                    const int la = rl[2 * mb], lb = rl[2 * mb + 1];
                    const float v00 = fmaf(-2.0f, acc[fi][0], m0.x);
                    const float v01 = fmaf(-2.0f, acc[fi][1], m1.x);
                    const float v10 = fmaf(-2.0f, acc[fi][2], m0.x);
                    const float v11 = fmaf(-2.0f, acc[fi][3], m1.x);
                    const float w00 = fmaf(-2.0f, acc[fi][0], sqa[2 * mb]);
                    const float w01 = fmaf(-2.0f, acc[fi][1], sqa[2 * mb]);
                    const float w10 = fmaf(-2.0f, acc[fi][2], sqa[2 * mb + 1]);
                    const float w11 = fmaf(-2.0f, acc[fi][3], sqa[2 * mb + 1]);
                    const bool s00 = (l0 == la), s01 = (l1 == la);
                    const bool s10 = (l0 == lb), s11 = (l1 == lb);
                    if (s00) { if (c0 != r0) hp[2*mb]   = fmaxf(hp[2*mb],   v00); }
                    else hn[2*mb]   = fminf(hn[2*mb],   v00);
                    if (s01) { if (c1 != r0) hp[2*mb]   = fmaxf(hp[2*mb],   v01); }
                    else hn[2*mb]   = fminf(hn[2*mb],   v01);
                    if (s10) { if (c0 != r1) hp[2*mb+1] = fmaxf(hp[2*mb+1], v10); }
                    else hn[2*mb+1] = fminf(hn[2*mb+1], v10);
                    if (s11) { if (c1 != r1) hp[2*mb+1] = fmaxf(hp[2*mb+1], v11); }
                    else hn[2*mb+1] = fminf(hn[2*mb+1], v11);
                    cp0 = fmaxf(cp0, fmaxf((s00 && c0 != r0) ? w00 : -1e30f,
                                           (s10 && c0 != r1) ? w10 : -1e30f));
                    cp1 = fmaxf(cp1, fmaxf((s01 && c1 != r0) ? w01 : -1e30f,
                                           (s11 && c1 != r1) ? w11 : -1e30f));
                    cn0 = fminf(cn0, fminf(s00 ? 1e30f : w00, s10 ? 1e30f : w10));
                    cn1 = fminf(cn1, fminf(s01 ? 1e30f : w01, s11 ? 1e30f : w11));
                }
                #pragma unroll
                for (int o = 4; o < 32; o <<= 1) {
                    cp0 = fmaxf(cp0, __shfl_xor_sync(0xFFFFFFFFu, cp0, o));
                    cp1 = fmaxf(cp1, __shfl_xor_sync(0xFFFFFFFFu, cp1, o));
                    cn0 = fminf(cn0, __shfl_xor_sync(0xFFFFFFFFu, cn0, o));
                    cn1 = fminf(cn1, __shfl_xor_sync(0xFFFFFFFFu, cn1, o));
                }
                if (lane < 4) {            // disjoint addresses: plain stores
                    wp[wy * 128 + cl]           = cp0;
                    wp[wy * 128 + cl + 1]       = cp1;
                    wp[512 + wy * 128 + cl]     = cn0;
                    wp[512 + wy * 128 + cl + 1] = cn1;
                }
            }
        }
    }

    // final column fold (last tile)
    __syncthreads();
    if (tid < 128) {
        const int ft = nt - 1;
        const float* fp = (const float*)(smem + OFF_CB + (ft & 1) * 4096);
        const float* fn = fp + 512;
        const int c = (bj0 + ft) * 128 + tid;
        float pv = fp[tid], qv = fn[tid];
        #pragma unroll
        for (int w = 1; w < 4; w++) {
            pv = fmaxf(pv, fp[w * 128 + tid]);
            qv = fminf(qv, fn[w * 128 + tid]);
        }
        if (pv > -1e29f) atomicMax(&g_apos[c], enc(pv));
        if (qv <  1e29f) atomicMin(&g_aneg[c], enc(qv));
    }

    // row folds -> global (fold the 4 lanes of each row quad first)
    #pragma unroll
    for (int o = 1; o < 4; o <<= 1) {
        #pragma unroll
        for (int i = 0; i < 4; i++) {
            hp[i] = fmaxf(hp[i], __shfl_xor_sync(0xFFFFFFFFu, hp[i], o));
            hn[i] = fminf(hn[i], __shfl_xor_sync(0xFFFFFFFFu, hn[i], o));
        }
    }
    if ((lane & 3) == 0) {
        #pragma unroll
        for (int i = 0; i < 4; i++) {
            if (hp[i] > -1e29f) atomicMax(&g_apos[trow[i]], enc(hp[i]));
            if (hn[i] <  1e29f) atomicMin(&g_aneg[trow[i]], enc(hn[i]));
        }
    }
}

// ---------------- finalize ----------------
__global__ void finalize_kernel(float* __restrict__ out, int n) {
    __shared__ float s_sum[32], s_cnt[32];
    float sum = 0.0f, cnt = 0.0f;
    for (int r = threadIdx.x; r < n; r += blockDim.x) {
        float hp = dec(g_apos[r]);
        float hn = dec(g_aneg[r]);
        if (hp > -1e29f && hn < 1e29f) {
            float sqa = g_meta[r].x;
            float dp = sqrtf(fmaxf(sqa + hp, 0.0f));
            float dn = sqrtf(fmaxf(sqa + hn, 0.0f));
            sum += fmaxf(dp - dn + 0.3f, 0.0f);
            cnt += 1.0f;
        }
    }
    int lane = threadIdx.x & 31, wid = threadIdx.x >> 5;
    #pragma unroll
    for (int o = 16; o > 0; o >>= 1) {
        sum += __shfl_xor_sync(0xFFFFFFFFu, sum, o);
        cnt += __shfl_xor_sync(0xFFFFFFFFu, cnt, o);
    }
    if (lane == 0) { s_sum[wid] = sum; s_cnt[wid] = cnt; }
    __syncthreads();
    if (threadIdx.x < 32) {
        int nw = blockDim.x >> 5;
        sum = (threadIdx.x < nw) ? s_sum[threadIdx.x] : 0.0f;
        cnt = (threadIdx.x < nw) ? s_cnt[threadIdx.x] : 0.0f;
        #pragma unroll
        for (int o = 16; o > 0; o >>= 1) {
            sum += __shfl_xor_sync(0xFFFFFFFFu, sum, o);
            cnt += __shfl_xor_sync(0xFFFFFFFFu, cnt, o);
        }
        if (threadIdx.x == 0) out[0] = (cnt > 0.0f) ? (sum / cnt) : 0.0f;
    }
}

// ---------------- launch (3 kernels) ----------------
extern "C" void kernel_launch(void* const* d_in, const int* in_sizes, int n_in,
                              void* d_out, int out_size) {
    const float* emb = (const float*)d_in[0];
    const int* labw = (const int*)d_in[1];
    int n = in_sizes[0] / DDIM;   // 8192

    cudaFuncSetAttribute(hmma_sym_kernel,
                         cudaFuncAttributeMaxDynamicSharedMemorySize, SMEM_TOTAL);

    pack_meta_kernel<<<(n * 16) / 256, 256>>>(labw, emb, n);
    hmma_sym_kernel<<<GRID_MAIN, 512, SMEM_TOTAL>>>();
    finalize_kernel<<<1, 1024>>>((float*)d_out, n);
}

// round 17
// speedup vs baseline: 5.3560x; 1.0470x over previous
#include <cuda_runtime.h>
#include <cuda_fp16.h>
#include <cstdint>

// BatchHardTripletLoss via fp16 hi/lo-split HMMA with Gram-symmetry halving.
// Round 17: no-reload k-step (8 LDSM up front, 24 MMA), 8-tile CTA groups
// (288 CTAs), 2-level epilogue shfl with wider colbuf, MLP-4 pack kernel.

#define NROWS  8192
#define DDIM   128
#define ROWBLKS 64
#define GRID_MAIN 288     // sum_{bi} ceil((64-bi)/8)
#define PSTRB   528       // smem row stride bytes (264 halfs)

// ---------------- device scratch ----------------
__device__ __align__(16) __half g_P[NROWS * 256];   // [row][0:128]=hi, [128:256]=lo
__device__ float2 g_meta[NROWS];                    // (sqnorm, label bits)
__device__ unsigned g_apos[NROWS];                  // encoded hardest-pos (max)
__device__ unsigned g_aneg[NROWS];                  // encoded hardest-neg (min)

// ---------------- helpers ----------------
__device__ __forceinline__ uint32_t smem_u32(const void* p) {
    uint32_t a;
    asm("{ .reg .u64 t; cvta.to.shared.u64 t, %1; cvt.u32.u64 %0, t; }" : "=r"(a) : "l"(p));
    return a;
}
__device__ __forceinline__ unsigned enc(float x) {
    int i = __float_as_int(x);
    return (i < 0) ? (unsigned)(~i) : ((unsigned)i | 0x80000000u);
}
__device__ __forceinline__ float dec(unsigned u) {
    int i = (u & 0x80000000u) ? (int)(u ^ 0x80000000u) : ~(int)u;
    return __int_as_float(i);
}
#define CP_ASYNC16(dst, src) \
    asm volatile("cp.async.cg.shared.global [%0], [%1], 16;" :: "r"(dst), "l"(src))
#define CP_COMMIT() asm volatile("cp.async.commit_group;" ::: "memory")
#define CP_WAIT0()  asm volatile("cp.async.wait_group 0;" ::: "memory")
#define LDSM4(R0, R1, R2, R3, ADDR) \
    asm volatile("ldmatrix.sync.aligned.m8n8.x4.shared.b16 {%0,%1,%2,%3}, [%4];" \
        : "=r"(R0), "=r"(R1), "=r"(R2), "=r"(R3) : "r"(ADDR))
#define MMA16816(C, A0, A1, A2, A3, B0, B1) \
    asm volatile("mma.sync.aligned.m16n8k16.row.col.f32.f16.f16.f32 " \
        "{%0,%1,%2,%3}, {%4,%5,%6,%7}, {%8,%9}, {%0,%1,%2,%3};" \
        : "+f"((C)[0]), "+f"((C)[1]), "+f"((C)[2]), "+f"((C)[3]) \
        : "r"(A0), "r"(A1), "r"(A2), "r"(A3), "r"(B0), "r"(B1))

// ---------------- fused prep: detect + labels + sqnorm + init + hi/lo pack ----
// 8 threads per row, 16 k-values (4 float4) each -> MLP 4.
__global__ void pack_meta_kernel(const int* __restrict__ words,
                                 const float* __restrict__ emb, int n) {
    __shared__ int s_odd;
    const int tid = threadIdx.x;
    if (tid == 0) s_odd = 0;
    __syncthreads();
    const int c = blockIdx.x * blockDim.x + tid;
    const int row = c >> 3;
    const int k16 = (c & 7) * 16;

    if ((c & 7) == 0) {
        if (words[2 * (row & (n / 2 - 1)) + 1]) atomicOr(&s_odd, 1);
    }

    const float4* p = (const float4*)(emb + row * DDIM + k16);
    float4 vv[4] = {p[0], p[1], p[2], p[3]};
    const float* v = (const float*)vv;
    __half hi[16], lo[16];
    float s = 0.0f;
    #pragma unroll
    for (int i = 0; i < 16; i++) {
        s = fmaf(v[i], v[i], s);
        hi[i] = __float2half_rn(v[i]);
        lo[i] = __float2half_rn(v[i] - __half2float(hi[i]));
    }
    #pragma unroll
    for (int o = 1; o < 8; o <<= 1) s += __shfl_xor_sync(0xFFFFFFFFu, s, o);

    *(uint4*)(g_P + row * 256 + k16)           = ((const uint4*)hi)[0];
    *(uint4*)(g_P + row * 256 + k16 + 8)       = ((const uint4*)hi)[1];
    *(uint4*)(g_P + row * 256 + 128 + k16)     = ((const uint4*)lo)[0];
    *(uint4*)(g_P + row * 256 + 128 + k16 + 8) = ((const uint4*)lo)[1];

    __syncthreads();
    if ((c & 7) == 0) {
        const int is64 = (s_odd == 0);
        int lab = words[is64 ? (2 * row) : row];
        g_meta[row] = make_float2(s, __int_as_float(lab));
        g_apos[row] = enc(-1e30f);
        g_aneg[row] = enc(1e30f);
    }
}

// ---------------- main symmetric HMMA kernel ----------------
#define OFF_A     0
#define OFF_B0    67584
#define OFF_B1    135168
#define OFF_MT0   202752
#define OFF_MT1   203776
#define OFF_CB    204800    // 2 buffers x (pos[4][2][128] + neg[4][2][128]) = 16KB
#define SMEM_TOTAL 221184

__global__ void __launch_bounds__(512, 1) hmma_sym_kernel() {
    extern __shared__ char smem[];
    const uint32_t sb = smem_u32(smem);
    const int tid = threadIdx.x, wid = tid >> 5, lane = tid & 31;
    const int wy = wid >> 2, wx = wid & 3;   // 4 row-groups x 4 col-groups

    // map blockIdx -> (bi, group of up to 8 column tiles)
    int id = blockIdx.x, bi = 0;
    for (; bi < ROWBLKS; bi++) {
        int cnt = (ROWBLKS - bi + 7) >> 3;
        if (id < cnt) break;
        id -= cnt;
    }
    const int bj0 = bi + 8 * id;
    const int nt = min(8, ROWBLKS - bj0);
    const int rowbase = bi * 128;

    // ---- prologue: A stripe (hi|lo), B tile 0, meta 0 ----
    #pragma unroll
    for (int i = 0; i < 8; i++) {
        int idx = tid + i * 512;
        int r = idx >> 5, cc = idx & 31;
        CP_ASYNC16(sb + OFF_A + r * PSTRB + cc * 16,
                   g_P + (size_t)(rowbase + r) * 256 + cc * 8);
    }
    CP_COMMIT();
    {
        const int cb = bj0 * 128;
        #pragma unroll
        for (int i = 0; i < 8; i++) {
            int idx = tid + i * 512;
            int r = idx >> 5, cc = idx & 31;
            CP_ASYNC16(sb + OFF_B0 + r * PSTRB + cc * 16,
                       g_P + (size_t)(cb + r) * 256 + cc * 8);
        }
        if (tid < 64)
            CP_ASYNC16(sb + OFF_MT0 + tid * 16, (const char*)(g_meta + cb) + tid * 16);
        CP_COMMIT();
    }

    // this thread's 4 anchor rows
    int   trow[4];
    int   rl[4];
    float sqa[4], hp[4], hn[4];
    #pragma unroll
    for (int mb = 0; mb < 2; mb++) {
        #pragma unroll
        for (int h = 0; h < 2; h++) {
            int r = rowbase + 32 * wy + 16 * mb + 8 * h + (lane >> 2);
            float2 m = g_meta[r];
            trow[2 * mb + h] = r;
            rl[2 * mb + h] = __float_as_int(m.y);
            sqa[2 * mb + h] = m.x;
            hp[2 * mb + h] = -1e30f;
            hn[2 * mb + h] = 1e30f;
        }
    }

    const uint32_t aAddr = sb + OFF_A
        + (uint32_t)(32 * wy + 8 * ((lane >> 3) & 1) + (lane & 7)) * PSTRB
        + (uint32_t)(8 * (lane >> 4)) * 2;
    const uint32_t bColOff = (uint32_t)(32 * wx) * PSTRB
        + (uint32_t)(8 * (lane >> 4) + (lane & 7)) * PSTRB
        + (uint32_t)(8 * ((lane >> 3) & 1)) * 2;

    for (int t = 0; t < nt; t++) {
        CP_WAIT0();
        __syncthreads();     // tile t resident; colbuf[(t-1)&1] writes visible

        if (t + 1 < nt) {    // prefetch next B + meta first (latency-critical)
            const uint32_t dstB = sb + (((t + 1) & 1) ? OFF_B1 : OFF_B0);
            const int cb = (bj0 + t + 1) * 128;
            #pragma unroll
            for (int i = 0; i < 8; i++) {
                int idx = tid + i * 512;
                int r = idx >> 5, cc = idx & 31;
                CP_ASYNC16(dstB + r * PSTRB + cc * 16,
                           g_P + (size_t)(cb + r) * 256 + cc * 8);
            }
            if (tid < 64)
                CP_ASYNC16(sb + (((t + 1) & 1) ? OFF_MT1 : OFF_MT0) + tid * 16,
                           (const char*)(g_meta + cb) + tid * 16);
            CP_COMMIT();
        }

        // deferred column fold for tile t-1 (overlaps with mainloop)
        if (t > 0 && tid < 256) {
            const float* fb = (const float*)(smem + OFF_CB + ((t - 1) & 1) * 8192)
                              + (tid >> 7) * 1024;   // pos half then neg half
            const int col = tid & 127;
            const int c = (bj0 + t - 1) * 128 + col;
            if (tid < 128) {
                float pv = fb[col];
                #pragma unroll
                for (int w = 1; w < 8; w++) pv = fmaxf(pv, fb[col + 128 * w]);
                if (pv > -1e29f) atomicMax(&g_apos[c], enc(pv));
            } else {
                float qv = fb[col];
                #pragma unroll
                for (int w = 1; w < 8; w++) qv = fminf(qv, fb[col + 128 * w]);
                if (qv <  1e29f) atomicMin(&g_aneg[c], enc(qv));
            }
        }

        const uint32_t bBase = sb + ((t & 1) ? OFF_B1 : OFF_B0) + bColOff;

        float acc[8][4];     // 32 rows x 32 cols per warp
        #pragma unroll
        for (int f = 0; f < 8; f++)
            #pragma unroll
            for (int e = 0; e < 4; e++) acc[f][e] = 0.0f;

        #pragma unroll
        for (int ks = 0; ks < 8; ks++) {
            uint32_t Ah[2][4], Al[2][4], Bh[2][4], Bl[2][4];
            #pragma unroll
            for (int mb = 0; mb < 2; mb++) {
                LDSM4(Ah[mb][0], Ah[mb][1], Ah[mb][2], Ah[mb][3],
                      aAddr + (uint32_t)(16 * mb * PSTRB) + (uint32_t)(32 * ks));
                LDSM4(Al[mb][0], Al[mb][1], Al[mb][2], Al[mb][3],
                      aAddr + (uint32_t)(16 * mb * PSTRB) + 256u + (uint32_t)(32 * ks));
            }
            #pragma unroll
            for (int nb = 0; nb < 2; nb++) {
                LDSM4(Bh[nb][0], Bh[nb][1], Bh[nb][2], Bh[nb][3],
                      bBase + (uint32_t)(nb * 16 * PSTRB) + (uint32_t)(32 * ks));
                LDSM4(Bl[nb][0], Bl[nb][1], Bl[nb][2], Bl[nb][3],
                      bBase + (uint32_t)(nb * 16 * PSTRB) + 256u + (uint32_t)(32 * ks));
            }
            // pass 1: hi_A * hi_B
            #pragma unroll
            for (int mb = 0; mb < 2; mb++)
                #pragma unroll
                for (int nb = 0; nb < 2; nb++) {
                    MMA16816(acc[mb * 4 + 2 * nb],
                             Ah[mb][0], Ah[mb][1], Ah[mb][2], Ah[mb][3],
                             Bh[nb][0], Bh[nb][1]);
                    MMA16816(acc[mb * 4 + 2 * nb + 1],
                             Ah[mb][0], Ah[mb][1], Ah[mb][2], Ah[mb][3],
                             Bh[nb][2], Bh[nb][3]);
                }
            // pass 2: hi_A * lo_B
            #pragma unroll
            for (int mb = 0; mb < 2; mb++)
                #pragma unroll
                for (int nb = 0; nb < 2; nb++) {
                    MMA16816(acc[mb * 4 + 2 * nb],
                             Ah[mb][0], Ah[mb][1], Ah[mb][2], Ah[mb][3],
                             Bl[nb][0], Bl[nb][1]);
                    MMA16816(acc[mb * 4 + 2 * nb + 1],
                             Ah[mb][0], Ah[mb][1], Ah[mb][2], Ah[mb][3],
                             Bl[nb][2], Bl[nb][3]);
                }
            // pass 3: lo_A * hi_B
            #pragma unroll
            for (int mb = 0; mb < 2; mb++)
                #pragma unroll
                for (int nb = 0; nb < 2; nb++) {
                    MMA16816(acc[mb * 4 + 2 * nb],
                             Al[mb][0], Al[mb][1], Al[mb][2], Al[mb][3],
                             Bh[nb][0], Bh[nb][1]);
                    MMA16816(acc[mb * 4 + 2 * nb + 1],
                             Al[mb][0], Al[mb][1], Al[mb][2], Al[mb][3],
                             Bh[nb][2], Bh[nb][3]);
                }
        }

        // ---- epilogue: row folds in regs; column partials (2-level shfl) ----
        {
            const float2* mp = (const float2*)(smem + ((t & 1) ? OFF_MT1 : OFF_MT0));
            float* wp = (float*)(smem + OFF_CB + (t & 1) * 8192);
            const int cgb = (bj0 + t) * 128;
            const int h = lane >> 4;
            #pragma unroll
            for (int j = 0; j < 4; j++) {
                const int cl = 32 * wx + 8 * j + 2 * (lane & 3);
                const float2 m0 = mp[cl];
                const float2 m1 = mp[cl + 1];
                const int c0 = cgb + cl, c1 = c0 + 1;
                const int l0 = __float_as_int(m0.y);
                const int l1 = __float_as_int(m1.y);
                float cp0 = -1e30f, cp1 = -1e30f, cn0 = 1e30f, cn1 = 1e30f;
                #pragma unroll
                for (int mb = 0; mb < 2; mb++) {
                    const int fi = mb * 4 + j;
                    const int r0 = trow[2 * mb], r1 = trow[2 * mb + 1];
                    const int la = rl[2 * mb], lb = rl[2 * mb + 1];
                    const float v00 = fmaf(-2.0f, acc[fi][0], m0.x);
                    const float v01 = fmaf(-2.0f, acc[fi][1], m1.x);
                    const float v10 = fmaf(-2.0f, acc[fi][2], m0.x);
                    const float v11 = fmaf(-2.0f, acc[fi][3], m1.x);
                    const float w00 = fmaf(-2.0f, acc[fi][0], sqa[2 * mb]);
                    const float w01 = fmaf(-2.0f, acc[fi][1], sqa[2 * mb]);
                    const float w10 = fmaf(-2.0f, acc[fi][2], sqa[2 * mb + 1]);
                    const float w11 = fmaf(-2.0f, acc[fi][3], sqa[2 * mb + 1]);
                    const bool s00 = (l0 == la), s01 = (l1 == la);
                    const bool s10 = (l0 == lb), s11 = (l1 == lb);
                    if (s00) { if (c0 != r0) hp[2*mb]   = fmaxf(hp[2*mb],   v00); }
                    else hn[2*mb]   = fminf(hn[2*mb],   v00);
                    if (s01) { if (c1 != r0) hp[2*mb]   = fmaxf(hp[2*mb],   v01); }
                    else hn[2*mb]   = fminf(hn[2*mb],   v01);
                    if (s10) { if (c0 != r1) hp[2*mb+1] = fmaxf(hp[2*mb+1], v10); }
                    else hn[2*mb+1] = fminf(hn[2*mb+1], v10);
                    if (s11) { if (c1 != r1) hp[2*mb+1] = fmaxf(hp[2*mb+1], v11); }
                    else hn[2*mb+1] = fminf(hn[2*mb+1], v11);
                    cp0 = fmaxf(cp0, fmaxf((s00 && c0 != r0) ? w00 : -1e30f,
                                           (s10 && c0 != r1) ? w10 : -1e30f));
                    cp1 = fmaxf(cp1, fmaxf((s01 && c1 != r0) ? w01 : -1e30f,
                                           (s11 && c1 != r1) ? w11 : -1e30f));
                    cn0 = fminf(cn0, fminf(s00 ? 1e30f : w00, s10 ? 1e30f : w10));
                    cn1 = fminf(cn1, fminf(s01 ? 1e30f : w01, s11 ? 1e30f : w11));
                }
                #pragma unroll
                for (int o = 4; o < 16; o <<= 1) {   // 2 levels; survivor per 16-half
                    cp0 = fmaxf(cp0, __shfl_xor_sync(0xFFFFFFFFu, cp0, o));
                    cp1 = fmaxf(cp1, __shfl_xor_sync(0xFFFFFFFFu, cp1, o));
                    cn0 = fminf(cn0, __shfl_xor_sync(0xFFFFFFFFu, cn0, o));
                    cn1 = fminf(cn1, __shfl_xor_sync(0xFFFFFFFFu, cn1, o));
                }
                if ((lane & 12) == 0) {    // lanes 0-3 (h=0), 16-19 (h=1)
                    const int base = wy * 256 + h * 128 + cl;
                    wp[base]            = cp0;
                    wp[base + 1]        = cp1;
                    wp[1024 + base]     = cn0;
                    wp[1024 + base + 1] = cn1;
                }
            }
        }
    }

    // final column fold (last tile)
    __syncthreads();
    if (tid < 256) {
        const int ft = nt - 1;
        const float* fb = (const float*)(smem + OFF_CB + (ft & 1) * 8192)
                          + (tid >> 7) * 1024;
        const int col = tid & 127;
        const int c = (bj0 + ft) * 128 + col;
        if (tid < 128) {
            float pv = fb[col];
            #pragma unroll
            for (int w = 1; w < 8; w++) pv = fmaxf(pv, fb[col + 128 * w]);
            if (pv > -1e29f) atomicMax(&g_apos[c], enc(pv));
        } else {
            float qv = fb[col];
            #pragma unroll
            for (int w = 1; w < 8; w++) qv = fminf(qv, fb[col + 128 * w]);
            if (qv <  1e29f) atomicMin(&g_aneg[c], enc(qv));
        }
    }

    // row folds -> global (fold the 4 lanes of each row quad first)
    #pragma unroll
    for (int o = 1; o < 4; o <<= 1) {
        #pragma unroll
        for (int i = 0; i < 4; i++) {
            hp[i] = fmaxf(hp[i], __shfl_xor_sync(0xFFFFFFFFu, hp[i], o));
            hn[i] = fminf(hn[i], __shfl_xor_sync(0xFFFFFFFFu, hn[i], o));
        }
    }
    if ((lane & 3) == 0) {
        #pragma unroll
        for (int i = 0; i < 4; i++) {
            if (hp[i] > -1e29f) atomicMax(&g_apos[trow[i]], enc(hp[i]));
            if (hn[i] <  1e29f) atomicMin(&g_aneg[trow[i]], enc(hn[i]));
        }
    }
}

// ---------------- finalize ----------------
__global__ void finalize_kernel(float* __restrict__ out, int n) {
    __shared__ float s_sum[32], s_cnt[32];
    float sum = 0.0f, cnt = 0.0f;
    for (int r = threadIdx.x; r < n; r += blockDim.x) {
        float hp = dec(g_apos[r]);
        float hn = dec(g_aneg[r]);
        if (hp > -1e29f && hn < 1e29f) {
            float sqa = g_meta[r].x;
            float dp = sqrtf(fmaxf(sqa + hp, 0.0f));
            float dn = sqrtf(fmaxf(sqa + hn, 0.0f));
            sum += fmaxf(dp - dn + 0.3f, 0.0f);
            cnt += 1.0f;
        }
    }
    int lane = threadIdx.x & 31, wid = threadIdx.x >> 5;
    #pragma unroll
    for (int o = 16; o > 0; o >>= 1) {
        sum += __shfl_xor_sync(0xFFFFFFFFu, sum, o);
        cnt += __shfl_xor_sync(0xFFFFFFFFu, cnt, o);
    }
    if (lane == 0) { s_sum[wid] = sum; s_cnt[wid] = cnt; }
    __syncthreads();
    if (threadIdx.x < 32) {
        int nw = blockDim.x >> 5;
        sum = (threadIdx.x < nw) ? s_sum[threadIdx.x] : 0.0f;
        cnt = (threadIdx.x < nw) ? s_cnt[threadIdx.x] : 0.0f;
        #pragma unroll
        for (int o = 16; o > 0; o >>= 1) {
            sum += __shfl_xor_sync(0xFFFFFFFFu, sum, o);
            cnt += __shfl_xor_sync(0xFFFFFFFFu, cnt, o);
        }
        if (threadIdx.x == 0) out[0] = (cnt > 0.0f) ? (sum / cnt) : 0.0f;
    }
}

// ---------------- launch (3 kernels) ----------------
extern "C" void kernel_launch(void* const* d_in, const int* in_sizes, int n_in,
                              void* d_out, int out_size) {
    const float* emb = (const float*)d_in[0];
    const int* labw = (const int*)d_in[1];
    int n = in_sizes[0] / DDIM;   // 8192

    cudaFuncSetAttribute(hmma_sym_kernel,
                         cudaFuncAttributeMaxDynamicSharedMemorySize, SMEM_TOTAL);

    pack_meta_kernel<<<(n * 8) / 256, 256>>>(labw, emb, n);
    hmma_sym_kernel<<<GRID_MAIN, 512, SMEM_TOTAL>>>();
    finalize_kernel<<<1, 1024>>>((float*)d_out, n);
}